// round 2
// baseline (speedup 1.0000x reference)
#include <cuda_runtime.h>
#include <math.h>

#define NN 50000
#define NE 640000
#define DIN 128
#define DH1 128
#define DH2 256

// ---------------- device scratch (allocation-free rule: __device__ globals) -------------
__device__ float g_xl1[NN * DH1];
__device__ float g_xr1[NN * DH1];
__device__ float g_res1[NN * DH1];
__device__ float g_h1[NN * DH1];
__device__ float g_xl2[NN * DH2];
__device__ float g_xr2[NN * DH2];
__device__ float g_res2[NN * DH2];
__device__ int   g_rowptr[NN + 1];
__device__ int   g_hist[NN];
__device__ int   g_cursor[NN];
__device__ int   g_srcs[NE];
__device__ int   g_src[NE];
__device__ int   g_dst[NE];
__device__ int   g_is64;

// ---------------- edge_index dtype detection + normalization ----------------
// If the buffer is int64 (little-endian, values < 2^31), every odd 32-bit word
// of the first 2048 words is the zero high-half. For int32 data those words are
// dst indices in [0, 50000) — all-zero probability is nil.
__global__ void detect_kernel(const unsigned int* __restrict__ w) {
    __shared__ int any_nonzero;
    if (threadIdx.x == 0) any_nonzero = 0;
    __syncthreads();
    unsigned int v = w[2 * threadIdx.x + 1];   // odd words, first 1024 pairs
    if (v != 0u) atomicOr(&any_nonzero, 1);
    __syncthreads();
    if (threadIdx.x == 0) g_is64 = any_nonzero ? 0 : 1;
}

__global__ void convert_kernel(const void* __restrict__ ei) {
    int e = blockIdx.x * blockDim.x + threadIdx.x;
    if (e >= NE) return;
    if (g_is64) {
        const long long* p = (const long long*)ei;
        g_src[e] = (int)p[e];
        g_dst[e] = (int)p[NE + e];
    } else {
        const int* p = (const int*)ei;
        g_src[e] = p[e];
        g_dst[e] = p[NE + e];
    }
}

// ---------------- CSR build ----------------
__global__ void hist_kernel() {
    int e = blockIdx.x * blockDim.x + threadIdx.x;
    if (e < NE) atomicAdd(&g_hist[g_dst[e]], 1);
}

__global__ void scan_kernel() {
    __shared__ int part[1024];
    int t = threadIdx.x;
    const int CH = (NN + 1023) / 1024;  // 49
    int lo = t * CH;
    int hi = lo + CH; if (hi > NN) hi = NN;
    int s = 0;
    for (int i = lo; i < hi; i++) s += g_hist[i];
    part[t] = s;
    __syncthreads();
    // Hillis-Steele inclusive scan
    for (int off = 1; off < 1024; off <<= 1) {
        int v = part[t];
        int u = (t >= off) ? part[t - off] : 0;
        __syncthreads();
        part[t] = v + u;
        __syncthreads();
    }
    int run = (t > 0) ? part[t - 1] : 0;
    for (int i = lo; i < hi; i++) {
        g_rowptr[i] = run;
        g_cursor[i] = run;
        run += g_hist[i];
    }
    if (t == 1023) g_rowptr[NN] = NE;
}

__global__ void scatter_kernel() {
    int e = blockIdx.x * blockDim.x + threadIdx.x;
    if (e < NE) {
        int p = atomicAdd(&g_cursor[g_dst[e]], 1);
        g_srcs[p] = g_src[e];
    }
}

// ---------------- fp32 tiled GEMM: C[M,N] = A[M,K] @ W[K,N] (+ bias) ----------------
// BM=64, BN=64, BK=16, 256 threads, 4x4 microtile per thread.
__global__ void __launch_bounds__(256) gemm_kernel(
    const float* __restrict__ A, const float* __restrict__ W,
    const float* __restrict__ bias, float* __restrict__ C,
    int M, int K, int N)
{
    __shared__ float As[16][65];  // [k][m], padded
    __shared__ float Bs[16][64];  // [k][n]
    int bn = blockIdx.x * 64;
    int bm = blockIdx.y * 64;
    int tid = threadIdx.x;
    int tr = tid / 16, tc = tid % 16;

    float acc[4][4];
#pragma unroll
    for (int i = 0; i < 4; i++)
#pragma unroll
        for (int j = 0; j < 4; j++) acc[i][j] = 0.f;

    int ar = tid >> 2, akb = (tid & 3) * 4;    // A tile load: 64 rows x 16 k
    int br = tid >> 4, bnb = (tid & 15) * 4;   // W tile load: 16 k x 64 n

    for (int k0 = 0; k0 < K; k0 += 16) {
        float4 av = make_float4(0.f, 0.f, 0.f, 0.f);
        if (bm + ar < M)
            av = *(const float4*)&A[(size_t)(bm + ar) * K + k0 + akb];
        As[akb + 0][ar] = av.x;
        As[akb + 1][ar] = av.y;
        As[akb + 2][ar] = av.z;
        As[akb + 3][ar] = av.w;
        float4 bv = *(const float4*)&W[(size_t)(k0 + br) * N + bn + bnb];
        *(float4*)&Bs[br][bnb] = bv;
        __syncthreads();
#pragma unroll
        for (int kk = 0; kk < 16; kk++) {
            float a0 = As[kk][tr * 4 + 0];
            float a1 = As[kk][tr * 4 + 1];
            float a2 = As[kk][tr * 4 + 2];
            float a3 = As[kk][tr * 4 + 3];
            float4 b = *(float4*)&Bs[kk][tc * 4];
            acc[0][0] = fmaf(a0, b.x, acc[0][0]); acc[0][1] = fmaf(a0, b.y, acc[0][1]);
            acc[0][2] = fmaf(a0, b.z, acc[0][2]); acc[0][3] = fmaf(a0, b.w, acc[0][3]);
            acc[1][0] = fmaf(a1, b.x, acc[1][0]); acc[1][1] = fmaf(a1, b.y, acc[1][1]);
            acc[1][2] = fmaf(a1, b.z, acc[1][2]); acc[1][3] = fmaf(a1, b.w, acc[1][3]);
            acc[2][0] = fmaf(a2, b.x, acc[2][0]); acc[2][1] = fmaf(a2, b.y, acc[2][1]);
            acc[2][2] = fmaf(a2, b.z, acc[2][2]); acc[2][3] = fmaf(a2, b.w, acc[2][3]);
            acc[3][0] = fmaf(a3, b.x, acc[3][0]); acc[3][1] = fmaf(a3, b.y, acc[3][1]);
            acc[3][2] = fmaf(a3, b.z, acc[3][2]); acc[3][3] = fmaf(a3, b.w, acc[3][3]);
        }
        __syncthreads();
    }

    float bb[4] = {0.f, 0.f, 0.f, 0.f};
    if (bias) {
#pragma unroll
        for (int j = 0; j < 4; j++) bb[j] = bias[bn + tc * 4 + j];
    }
#pragma unroll
    for (int i = 0; i < 4; i++) {
        int row = bm + tr * 4 + i;
        if (row < M) {
            float4 o;
            o.x = acc[i][0] + bb[0];
            o.y = acc[i][1] + bb[1];
            o.z = acc[i][2] + bb[2];
            o.w = acc[i][3] + bb[3];
            *(float4*)&C[(size_t)row * N + bn + tc * 4] = o;
        }
    }
}

// ---------------- fused edge pass: warp-per-dst, online softmax ----------------
template <int F>
__global__ void __launch_bounds__(256) edge_kernel(
    const float* __restrict__ xl, const float* __restrict__ xr,
    const float* __restrict__ att, const float* __restrict__ res,
    float* __restrict__ out, int apply_elu)
{
    constexpr int V = F / 32;  // floats per lane (4 or 8)
    int warp = (blockIdx.x * blockDim.x + threadIdx.x) >> 5;
    int lane = threadIdx.x & 31;
    if (warp >= NN) return;
    int dst = warp;
    const int base = lane * V;

    float a[V], xrv[V], acc[V];
#pragma unroll
    for (int j = 0; j < V; j += 4) {
        float4 t = *(const float4*)&att[base + j];
        a[j] = t.x; a[j + 1] = t.y; a[j + 2] = t.z; a[j + 3] = t.w;
        float4 r = *(const float4*)&xr[(size_t)dst * F + base + j];
        xrv[j] = r.x; xrv[j + 1] = r.y; xrv[j + 2] = r.z; xrv[j + 3] = r.w;
    }
#pragma unroll
    for (int j = 0; j < V; j++) acc[j] = 0.f;

    float emax = -INFINITY, denom = 0.f;
    int p0 = g_rowptr[dst], p1 = g_rowptr[dst + 1];

    for (int p = p0; p < p1; p++) {
        int s = g_srcs[p];
        float xlv[V];
#pragma unroll
        for (int j = 0; j < V; j += 4) {
            float4 t = *(const float4*)&xl[(size_t)s * F + base + j];
            xlv[j] = t.x; xlv[j + 1] = t.y; xlv[j + 2] = t.z; xlv[j + 3] = t.w;
        }
        float partial = 0.f;
#pragma unroll
        for (int j = 0; j < V; j++) {
            float h = xlv[j] + xrv[j];
            float lr = h > 0.f ? h : 0.2f * h;
            partial = fmaf(a[j], lr, partial);
        }
#pragma unroll
        for (int off = 16; off > 0; off >>= 1)
            partial += __shfl_xor_sync(0xffffffffu, partial, off);
        float e = partial;
        float nm = fmaxf(emax, e);
        float sc = __expf(emax - nm);   // 0 on first edge (emax = -inf)
        float we = __expf(e - nm);
        denom = denom * sc + we;
#pragma unroll
        for (int j = 0; j < V; j++) acc[j] = fmaf(we, xlv[j], acc[j] * sc);
        emax = nm;
    }

    float inv = 1.0f / (denom + 1e-16f);
#pragma unroll
    for (int j = 0; j < V; j += 4) {
        float4 r = *(const float4*)&res[(size_t)dst * F + base + j];
        float4 o;
        o.x = fmaf(acc[j + 0], inv, r.x);
        o.y = fmaf(acc[j + 1], inv, r.y);
        o.z = fmaf(acc[j + 2], inv, r.z);
        o.w = fmaf(acc[j + 3], inv, r.w);
        if (apply_elu) {
            o.x = o.x > 0.f ? o.x : expm1f(o.x);
            o.y = o.y > 0.f ? o.y : expm1f(o.y);
            o.z = o.z > 0.f ? o.z : expm1f(o.z);
            o.w = o.w > 0.f ? o.w : expm1f(o.w);
        }
        *(float4*)&out[(size_t)dst * F + base + j] = o;
    }
}

// ---------------- launch ----------------
extern "C" void kernel_launch(void* const* d_in, const int* in_sizes, int n_in,
                              void* d_out, int out_size)
{
    const float* x     = (const float*)d_in[0];
    const void*  ei    = d_in[1];
    const float* Wl1   = (const float*)d_in[2];
    const float* Wr1   = (const float*)d_in[3];
    const float* att1  = (const float*)d_in[4];
    const float* Wres1 = (const float*)d_in[5];
    const float* b1    = (const float*)d_in[6];
    const float* Wl2   = (const float*)d_in[7];
    const float* Wr2   = (const float*)d_in[8];
    const float* att2  = (const float*)d_in[9];
    const float* Wres2 = (const float*)d_in[10];
    const float* b2    = (const float*)d_in[11];

    float *xl1, *xr1, *res1, *h1, *xl2, *xr2, *res2;
    int* histp;
    cudaGetSymbolAddress((void**)&xl1,  g_xl1);
    cudaGetSymbolAddress((void**)&xr1,  g_xr1);
    cudaGetSymbolAddress((void**)&res1, g_res1);
    cudaGetSymbolAddress((void**)&h1,   g_h1);
    cudaGetSymbolAddress((void**)&xl2,  g_xl2);
    cudaGetSymbolAddress((void**)&xr2,  g_xr2);
    cudaGetSymbolAddress((void**)&res2, g_res2);
    cudaGetSymbolAddress((void**)&histp, g_hist);

    // Normalize edge_index (handles both int32 and int64 layouts)
    detect_kernel<<<1, 1024>>>((const unsigned int*)ei);
    convert_kernel<<<(NE + 255) / 256, 256>>>(ei);

    // CSR build (graph identical for both layers)
    cudaMemsetAsync(histp, 0, NN * sizeof(int));
    hist_kernel<<<(NE + 255) / 256, 256>>>();
    scan_kernel<<<1, 1024>>>();
    scatter_kernel<<<(NE + 255) / 256, 256>>>();

    const int MB = (NN + 63) / 64;  // 782

    // Layer 1 GEMMs (128 -> 128)
    gemm_kernel<<<dim3(DH1 / 64, MB), 256>>>(x, Wl1,   nullptr, xl1,  NN, DIN, DH1);
    gemm_kernel<<<dim3(DH1 / 64, MB), 256>>>(x, Wr1,   nullptr, xr1,  NN, DIN, DH1);
    gemm_kernel<<<dim3(DH1 / 64, MB), 256>>>(x, Wres1, b1,      res1, NN, DIN, DH1);

    // Layer 1 edge aggregation + residual + ELU
    edge_kernel<DH1><<<(NN * 32 + 255) / 256, 256>>>(xl1, xr1, att1, res1, h1, 1);

    // Layer 2 GEMMs (128 -> 256)
    gemm_kernel<<<dim3(DH2 / 64, MB), 256>>>(h1, Wl2,   nullptr, xl2,  NN, DH1, DH2);
    gemm_kernel<<<dim3(DH2 / 64, MB), 256>>>(h1, Wr2,   nullptr, xr2,  NN, DH1, DH2);
    gemm_kernel<<<dim3(DH2 / 64, MB), 256>>>(h1, Wres2, b2,      res2, NN, DH1, DH2);

    // Layer 2 edge aggregation + residual -> final output
    edge_kernel<DH2><<<(NN * 32 + 255) / 256, 256>>>(xl2, xr2, att2, res2, (float*)d_out, 0);
}

// round 3
// speedup vs baseline: 1.5383x; 1.5383x over previous
#include <cuda_runtime.h>
#include <math.h>

#define NN 50000
#define NE 640000
#define DIN 128
#define DH1 128
#define DH2 256

// ---------------- device scratch ----------------
__device__ float g_xl1[NN * DH1];
__device__ float g_xr1[NN * DH1];
__device__ float g_res1[NN * DH1];
__device__ float g_h1[NN * DH1];
__device__ float g_xl2[NN * DH2];
__device__ float g_xr2[NN * DH2];
__device__ float g_res2[NN * DH2];
__device__ int   g_rowptr[NN + 1];
__device__ int   g_hist[NN];
__device__ int   g_cursor[NN];
__device__ int   g_srcs[NE];
__device__ int   g_src[NE];
__device__ int   g_dst[NE];
__device__ int   g_is64;
#define SCAN_NB 98
__device__ int   g_bsum[SCAN_NB];
__device__ int   g_boff[SCAN_NB];

// ---------------- edge_index dtype detection + conversion + histogram ----------------
__global__ void detect_kernel(const unsigned int* __restrict__ w) {
    __shared__ int any_nonzero;
    if (threadIdx.x == 0) any_nonzero = 0;
    __syncthreads();
    unsigned int v = w[2 * threadIdx.x + 1];
    if (v != 0u) atomicOr(&any_nonzero, 1);
    __syncthreads();
    if (threadIdx.x == 0) g_is64 = any_nonzero ? 0 : 1;
}

__global__ void convert_hist_kernel(const void* __restrict__ ei) {
    int e = blockIdx.x * blockDim.x + threadIdx.x;
    if (e >= NE) return;
    int s, d;
    if (g_is64) {
        const long long* p = (const long long*)ei;
        s = (int)p[e]; d = (int)p[NE + e];
    } else {
        const int* p = (const int*)ei;
        s = p[e]; d = p[NE + e];
    }
    g_src[e] = s;
    g_dst[e] = d;
    atomicAdd(&g_hist[d], 1);
}

// ---------------- parallel 3-pass exclusive scan of g_hist -> g_rowptr ----------------
__global__ void scan_pass1() {
    __shared__ int sh[512];
    int t = threadIdx.x;
    int i = blockIdx.x * 512 + t;
    int v = (i < NN) ? g_hist[i] : 0;
    sh[t] = v;
    __syncthreads();
    for (int off = 1; off < 512; off <<= 1) {
        int u = (t >= off) ? sh[t - off] : 0;
        __syncthreads();
        sh[t] += u;
        __syncthreads();
    }
    if (i < NN) g_rowptr[i] = sh[t] - v;   // local exclusive
    if (t == 511) g_bsum[blockIdx.x] = sh[511];
}

__global__ void scan_pass2() {
    __shared__ int sh[128];
    int t = threadIdx.x;
    int v = (t < SCAN_NB) ? g_bsum[t] : 0;
    sh[t] = v;
    __syncthreads();
    for (int off = 1; off < 128; off <<= 1) {
        int u = (t >= off) ? sh[t - off] : 0;
        __syncthreads();
        sh[t] += u;
        __syncthreads();
    }
    if (t < SCAN_NB) g_boff[t] = sh[t] - v;  // exclusive
    if (t == 0) g_rowptr[NN] = NE;
}

__global__ void scan_pass3() {
    int i = blockIdx.x * 512 + threadIdx.x;
    if (i < NN) {
        int r = g_rowptr[i] + g_boff[blockIdx.x];
        g_rowptr[i] = r;
        g_cursor[i] = r;
    }
}

__global__ void scatter_kernel() {
    int e = blockIdx.x * blockDim.x + threadIdx.x;
    if (e < NE) {
        int p = atomicAdd(&g_cursor[g_dst[e]], 1);
        g_srcs[p] = g_src[e];
    }
}

// ---------------- tf32 tensor-core GEMM: C[M,N] = A[M,K] @ W[K,N] (+bias) ----------------
// BM=128, BN=64, BK=16. 256 threads = 8 warps, warp grid 4(M) x 2(N), warp tile 32x32.
// mma.sync.aligned.m16n8k8 tf32. fp32->tf32 conversion happens once at smem staging.
__device__ __forceinline__ unsigned f2tf32(float f) {
    unsigned u;
    asm("cvt.rna.tf32.f32 %0, %1;" : "=r"(u) : "f"(f));
    return u;
}

#define AS_STRIDE 132
#define BS_STRIDE 68

__global__ void __launch_bounds__(256) gemm_tf32_kernel(
    const float* __restrict__ A, const float* __restrict__ W,
    const float* __restrict__ bias, float* __restrict__ C,
    int M, int K, int N)
{
    __shared__ unsigned As[16 * AS_STRIDE];  // [k][m]
    __shared__ unsigned Bs[16 * BS_STRIDE];  // [k][n]

    int tid = threadIdx.x;
    int bm = blockIdx.y * 128;
    int bn = blockIdx.x * 64;

    int warpId = tid >> 5;
    int lane = tid & 31;
    int gid = lane >> 2;        // 0..7
    int tig = lane & 3;         // 0..3
    int warp_m = warpId & 3;    // 4 warps over M
    int warp_n = warpId >> 2;   // 2 warps over N

    float acc[2][4][4];
#pragma unroll
    for (int mt = 0; mt < 2; mt++)
#pragma unroll
        for (int nt = 0; nt < 4; nt++)
#pragma unroll
            for (int r = 0; r < 4; r++) acc[mt][nt][r] = 0.f;

    // A staging: thread t loads row = t>>1, k-offsets (t&1)*8 .. +7  (2 float4)
    int a_row = tid >> 1;
    int a_koff = (tid & 1) * 8;
    // B staging: thread t loads k-row = t>>4, n-offset (t&15)*4 (1 float4)
    int b_row = tid >> 4;
    int b_noff = (tid & 15) * 4;

    const bool a_valid = (bm + a_row) < M;
    const float* a_ptr = A + (size_t)(bm + a_row) * K + a_koff;
    const float* w_ptr = W + (size_t)b_row * N + bn + b_noff;

    for (int k0 = 0; k0 < K; k0 += 16) {
        // stage A (transpose to [k][m], convert to tf32)
        float4 v0 = make_float4(0.f, 0.f, 0.f, 0.f), v1 = v0;
        if (a_valid) {
            v0 = *(const float4*)(a_ptr + k0);
            v1 = *(const float4*)(a_ptr + k0 + 4);
        }
        As[(a_koff + 0) * AS_STRIDE + a_row] = f2tf32(v0.x);
        As[(a_koff + 1) * AS_STRIDE + a_row] = f2tf32(v0.y);
        As[(a_koff + 2) * AS_STRIDE + a_row] = f2tf32(v0.z);
        As[(a_koff + 3) * AS_STRIDE + a_row] = f2tf32(v0.w);
        As[(a_koff + 4) * AS_STRIDE + a_row] = f2tf32(v1.x);
        As[(a_koff + 5) * AS_STRIDE + a_row] = f2tf32(v1.y);
        As[(a_koff + 6) * AS_STRIDE + a_row] = f2tf32(v1.z);
        As[(a_koff + 7) * AS_STRIDE + a_row] = f2tf32(v1.w);
        // stage B
        float4 bvec = *(const float4*)(w_ptr + (size_t)k0 * N);
        uint4 bw;
        bw.x = f2tf32(bvec.x); bw.y = f2tf32(bvec.y);
        bw.z = f2tf32(bvec.z); bw.w = f2tf32(bvec.w);
        *(uint4*)&Bs[b_row * BS_STRIDE + b_noff] = bw;
        __syncthreads();

#pragma unroll
        for (int s = 0; s < 2; s++) {
            int kb = s * 8;
            unsigned afr[2][4];
#pragma unroll
            for (int mt = 0; mt < 2; mt++) {
                int rm = warp_m * 32 + mt * 16;
                afr[mt][0] = As[(kb + tig) * AS_STRIDE + rm + gid];
                afr[mt][1] = As[(kb + tig) * AS_STRIDE + rm + gid + 8];
                afr[mt][2] = As[(kb + tig + 4) * AS_STRIDE + rm + gid];
                afr[mt][3] = As[(kb + tig + 4) * AS_STRIDE + rm + gid + 8];
            }
#pragma unroll
            for (int nt = 0; nt < 4; nt++) {
                int cn = warp_n * 32 + nt * 8;
                unsigned b0 = Bs[(kb + tig) * BS_STRIDE + cn + gid];
                unsigned b1 = Bs[(kb + tig + 4) * BS_STRIDE + cn + gid];
#pragma unroll
                for (int mt = 0; mt < 2; mt++) {
                    asm volatile(
                        "mma.sync.aligned.m16n8k8.row.col.f32.tf32.tf32.f32 "
                        "{%0,%1,%2,%3}, {%4,%5,%6,%7}, {%8,%9}, {%0,%1,%2,%3};"
                        : "+f"(acc[mt][nt][0]), "+f"(acc[mt][nt][1]),
                          "+f"(acc[mt][nt][2]), "+f"(acc[mt][nt][3])
                        : "r"(afr[mt][0]), "r"(afr[mt][1]),
                          "r"(afr[mt][2]), "r"(afr[mt][3]),
                          "r"(b0), "r"(b1));
                }
            }
        }
        __syncthreads();
    }

    // epilogue
#pragma unroll
    for (int mt = 0; mt < 2; mt++) {
#pragma unroll
        for (int nt = 0; nt < 4; nt++) {
            int col = bn + warp_n * 32 + nt * 8 + tig * 2;
            float bx = 0.f, by = 0.f;
            if (bias) { bx = bias[col]; by = bias[col + 1]; }
            int r0 = bm + warp_m * 32 + mt * 16 + gid;
            if (r0 < M) {
                float2 o = make_float2(acc[mt][nt][0] + bx, acc[mt][nt][1] + by);
                *(float2*)&C[(size_t)r0 * N + col] = o;
            }
            int r1 = r0 + 8;
            if (r1 < M) {
                float2 o = make_float2(acc[mt][nt][2] + bx, acc[mt][nt][3] + by);
                *(float2*)&C[(size_t)r1 * N + col] = o;
            }
        }
    }
}

// ---------------- fused edge pass: warp-per-dst, online softmax ----------------
template <int F>
__global__ void __launch_bounds__(256) edge_kernel(
    const float* __restrict__ xl, const float* __restrict__ xr,
    const float* __restrict__ att, const float* __restrict__ res,
    float* __restrict__ out, int apply_elu)
{
    constexpr int V = F / 32;
    int warp = (blockIdx.x * blockDim.x + threadIdx.x) >> 5;
    int lane = threadIdx.x & 31;
    if (warp >= NN) return;
    int dst = warp;
    const int base = lane * V;

    float a[V], xrv[V], acc[V];
#pragma unroll
    for (int j = 0; j < V; j += 4) {
        float4 t = *(const float4*)&att[base + j];
        a[j] = t.x; a[j + 1] = t.y; a[j + 2] = t.z; a[j + 3] = t.w;
        float4 r = *(const float4*)&xr[(size_t)dst * F + base + j];
        xrv[j] = r.x; xrv[j + 1] = r.y; xrv[j + 2] = r.z; xrv[j + 3] = r.w;
    }
#pragma unroll
    for (int j = 0; j < V; j++) acc[j] = 0.f;

    float emax = -INFINITY, denom = 0.f;
    int p0 = g_rowptr[dst], p1 = g_rowptr[dst + 1];

    for (int p = p0; p < p1; p++) {
        int s = g_srcs[p];
        float xlv[V];
#pragma unroll
        for (int j = 0; j < V; j += 4) {
            float4 t = *(const float4*)&xl[(size_t)s * F + base + j];
            xlv[j] = t.x; xlv[j + 1] = t.y; xlv[j + 2] = t.z; xlv[j + 3] = t.w;
        }
        float partial = 0.f;
#pragma unroll
        for (int j = 0; j < V; j++) {
            float h = xlv[j] + xrv[j];
            float lr = h > 0.f ? h : 0.2f * h;
            partial = fmaf(a[j], lr, partial);
        }
#pragma unroll
        for (int off = 16; off > 0; off >>= 1)
            partial += __shfl_xor_sync(0xffffffffu, partial, off);
        float e = partial;
        float nm = fmaxf(emax, e);
        float sc = __expf(emax - nm);
        float we = __expf(e - nm);
        denom = denom * sc + we;
#pragma unroll
        for (int j = 0; j < V; j++) acc[j] = fmaf(we, xlv[j], acc[j] * sc);
        emax = nm;
    }

    float inv = 1.0f / (denom + 1e-16f);
#pragma unroll
    for (int j = 0; j < V; j += 4) {
        float4 r = *(const float4*)&res[(size_t)dst * F + base + j];
        float4 o;
        o.x = fmaf(acc[j + 0], inv, r.x);
        o.y = fmaf(acc[j + 1], inv, r.y);
        o.z = fmaf(acc[j + 2], inv, r.z);
        o.w = fmaf(acc[j + 3], inv, r.w);
        if (apply_elu) {
            o.x = o.x > 0.f ? o.x : expm1f(o.x);
            o.y = o.y > 0.f ? o.y : expm1f(o.y);
            o.z = o.z > 0.f ? o.z : expm1f(o.z);
            o.w = o.w > 0.f ? o.w : expm1f(o.w);
        }
        *(float4*)&out[(size_t)dst * F + base + j] = o;
    }
}

// ---------------- launch ----------------
extern "C" void kernel_launch(void* const* d_in, const int* in_sizes, int n_in,
                              void* d_out, int out_size)
{
    const float* x     = (const float*)d_in[0];
    const void*  ei    = d_in[1];
    const float* Wl1   = (const float*)d_in[2];
    const float* Wr1   = (const float*)d_in[3];
    const float* att1  = (const float*)d_in[4];
    const float* Wres1 = (const float*)d_in[5];
    const float* b1    = (const float*)d_in[6];
    const float* Wl2   = (const float*)d_in[7];
    const float* Wr2   = (const float*)d_in[8];
    const float* att2  = (const float*)d_in[9];
    const float* Wres2 = (const float*)d_in[10];
    const float* b2    = (const float*)d_in[11];

    float *xl1, *xr1, *res1, *h1, *xl2, *xr2, *res2;
    int* histp;
    cudaGetSymbolAddress((void**)&xl1,  g_xl1);
    cudaGetSymbolAddress((void**)&xr1,  g_xr1);
    cudaGetSymbolAddress((void**)&res1, g_res1);
    cudaGetSymbolAddress((void**)&h1,   g_h1);
    cudaGetSymbolAddress((void**)&xl2,  g_xl2);
    cudaGetSymbolAddress((void**)&xr2,  g_xr2);
    cudaGetSymbolAddress((void**)&res2, g_res2);
    cudaGetSymbolAddress((void**)&histp, g_hist);

    // CSR build
    cudaMemsetAsync(histp, 0, NN * sizeof(int));
    detect_kernel<<<1, 1024>>>((const unsigned int*)ei);
    convert_hist_kernel<<<(NE + 255) / 256, 256>>>(ei);
    scan_pass1<<<SCAN_NB, 512>>>();
    scan_pass2<<<1, 128>>>();
    scan_pass3<<<SCAN_NB, 512>>>();
    scatter_kernel<<<(NE + 255) / 256, 256>>>();

    const int MB = (NN + 127) / 128;  // 391

    // Layer 1 GEMMs (128 -> 128), tf32 tensor cores
    gemm_tf32_kernel<<<dim3(DH1 / 64, MB), 256>>>(x, Wl1,   nullptr, xl1,  NN, DIN, DH1);
    gemm_tf32_kernel<<<dim3(DH1 / 64, MB), 256>>>(x, Wr1,   nullptr, xr1,  NN, DIN, DH1);
    gemm_tf32_kernel<<<dim3(DH1 / 64, MB), 256>>>(x, Wres1, b1,      res1, NN, DIN, DH1);

    // Layer 1 edge aggregation + residual + ELU
    edge_kernel<DH1><<<(NN * 32 + 255) / 256, 256>>>(xl1, xr1, att1, res1, h1, 1);

    // Layer 2 GEMMs (128 -> 256)
    gemm_tf32_kernel<<<dim3(DH2 / 64, MB), 256>>>(h1, Wl2,   nullptr, xl2,  NN, DH1, DH2);
    gemm_tf32_kernel<<<dim3(DH2 / 64, MB), 256>>>(h1, Wr2,   nullptr, xr2,  NN, DH1, DH2);
    gemm_tf32_kernel<<<dim3(DH2 / 64, MB), 256>>>(h1, Wres2, b2,      res2, NN, DH1, DH2);

    // Layer 2 edge aggregation + residual -> final output
    edge_kernel<DH2><<<(NN * 32 + 255) / 256, 256>>>(xl2, xr2, att2, res2, (float*)d_out, 0);
}

// round 4
// speedup vs baseline: 1.6020x; 1.0414x over previous
#include <cuda_runtime.h>
#include <math.h>

#define NN 50000
#define NE 640000
#define DIN 128
#define DH1 128
#define DH2 256
#define NT1 (3 * DH1)   // 384
#define NT2 (3 * DH2)   // 768

// ---------------- device scratch ----------------
__device__ float g_c1[NN * NT1];     // [xl1 | xr1 | res1] per node
__device__ float g_h1[NN * DH1];
__device__ float g_c2[NN * NT2];     // [xl2 | xr2 | res2] per node
__device__ float g_W1[DIN * NT1];
__device__ float g_W2[DH1 * NT2];
__device__ float g_b1p[NT1];
__device__ float g_b2p[NT2];
__device__ int   g_rowptr[NN + 1];
__device__ int   g_hist[NN];
__device__ int   g_cursor[NN];
__device__ int   g_srcs[NE];
__device__ int   g_src[NE];
__device__ int   g_dst[NE];
__device__ int   g_is64;
#define SCAN_NB 98
__device__ int   g_bsum[SCAN_NB];
__device__ int   g_boff[SCAN_NB];

// ---------------- weight packing: Wp[K][3F] = [Wl | Wr | Wres], bias padded ----------
__global__ void pack_kernel(const float* __restrict__ Wl, const float* __restrict__ Wr,
                            const float* __restrict__ Wres, const float* __restrict__ b,
                            float* __restrict__ Wp, float* __restrict__ bp, int K, int F) {
    int idx = blockIdx.x * blockDim.x + threadIdx.x;
    int NT = 3 * F;
    if (idx < K * NT) {
        int k = idx / NT, c = idx % NT;
        float v = (c < F) ? Wl[k * F + c]
                : (c < 2 * F) ? Wr[k * F + (c - F)]
                : Wres[k * F + (c - 2 * F)];
        Wp[idx] = v;
    }
    if (idx < NT) bp[idx] = (idx < 2 * F) ? 0.f : b[idx - 2 * F];
}

// ---------------- edge_index dtype detection + conversion + histogram ----------------
__global__ void detect_kernel(const unsigned int* __restrict__ w) {
    __shared__ int any_nonzero;
    if (threadIdx.x == 0) any_nonzero = 0;
    __syncthreads();
    unsigned int v = w[2 * threadIdx.x + 1];
    if (v != 0u) atomicOr(&any_nonzero, 1);
    __syncthreads();
    if (threadIdx.x == 0) g_is64 = any_nonzero ? 0 : 1;
}

__global__ void convert_hist_kernel(const void* __restrict__ ei) {
    int e = blockIdx.x * blockDim.x + threadIdx.x;
    if (e >= NE) return;
    int s, d;
    if (g_is64) {
        const long long* p = (const long long*)ei;
        s = (int)p[e]; d = (int)p[NE + e];
    } else {
        const int* p = (const int*)ei;
        s = p[e]; d = p[NE + e];
    }
    g_src[e] = s;
    g_dst[e] = d;
    atomicAdd(&g_hist[d], 1);
}

// ---------------- parallel 3-pass exclusive scan ----------------
__global__ void scan_pass1() {
    __shared__ int sh[512];
    int t = threadIdx.x;
    int i = blockIdx.x * 512 + t;
    int v = (i < NN) ? g_hist[i] : 0;
    sh[t] = v;
    __syncthreads();
    for (int off = 1; off < 512; off <<= 1) {
        int u = (t >= off) ? sh[t - off] : 0;
        __syncthreads();
        sh[t] += u;
        __syncthreads();
    }
    if (i < NN) g_rowptr[i] = sh[t] - v;
    if (t == 511) g_bsum[blockIdx.x] = sh[511];
}

__global__ void scan_pass2() {
    __shared__ int sh[128];
    int t = threadIdx.x;
    int v = (t < SCAN_NB) ? g_bsum[t] : 0;
    sh[t] = v;
    __syncthreads();
    for (int off = 1; off < 128; off <<= 1) {
        int u = (t >= off) ? sh[t - off] : 0;
        __syncthreads();
        sh[t] += u;
        __syncthreads();
    }
    if (t < SCAN_NB) g_boff[t] = sh[t] - v;
    if (t == 0) g_rowptr[NN] = NE;
}

__global__ void scan_pass3() {
    int i = blockIdx.x * 512 + threadIdx.x;
    if (i < NN) {
        int r = g_rowptr[i] + g_boff[blockIdx.x];
        g_rowptr[i] = r;
        g_cursor[i] = r;
    }
}

__global__ void scatter_kernel() {
    int e = blockIdx.x * blockDim.x + threadIdx.x;
    if (e < NE) {
        int p = atomicAdd(&g_cursor[g_dst[e]], 1);
        g_srcs[p] = g_src[e];
    }
}

// ---------------- tf32 tensor-core GEMM, register-prefetch pipelined ----------------
__device__ __forceinline__ unsigned f2tf32(float f) {
    unsigned u;
    asm("cvt.rna.tf32.f32 %0, %1;" : "=r"(u) : "f"(f));
    return u;
}

#define AS_STRIDE 132
#define BS_STRIDE 68

__global__ void __launch_bounds__(256) gemm_tf32_kernel(
    const float* __restrict__ A, const float* __restrict__ W,
    const float* __restrict__ bias, float* __restrict__ C,
    int M, int K, int N)
{
    __shared__ unsigned As[16 * AS_STRIDE];  // [k][m]
    __shared__ unsigned Bs[16 * BS_STRIDE];  // [k][n]

    int tid = threadIdx.x;
    int bm = blockIdx.y * 128;
    int bn = blockIdx.x * 64;

    int warpId = tid >> 5;
    int lane = tid & 31;
    int gid = lane >> 2;
    int tig = lane & 3;
    int warp_m = warpId & 3;
    int warp_n = warpId >> 2;

    float acc[2][4][4];
#pragma unroll
    for (int mt = 0; mt < 2; mt++)
#pragma unroll
        for (int nt = 0; nt < 4; nt++)
#pragma unroll
            for (int r = 0; r < 4; r++) acc[mt][nt][r] = 0.f;

    int a_row = tid >> 1;
    int a_koff = (tid & 1) * 8;
    int b_row = tid >> 4;
    int b_noff = (tid & 15) * 4;

    const bool a_valid = (bm + a_row) < M;
    const float* a_ptr = A + (size_t)(bm + a_row) * K + a_koff;
    const float* w_ptr = W + (size_t)b_row * N + bn + b_noff;

    // prologue: fetch first tile into registers
    float4 v0 = make_float4(0.f, 0.f, 0.f, 0.f), v1 = v0;
    if (a_valid) {
        v0 = *(const float4*)(a_ptr);
        v1 = *(const float4*)(a_ptr + 4);
    }
    float4 bvec = *(const float4*)(w_ptr);

    for (int k0 = 0; k0 < K; k0 += 16) {
        // stage current tile (convert to tf32)
        As[(a_koff + 0) * AS_STRIDE + a_row] = f2tf32(v0.x);
        As[(a_koff + 1) * AS_STRIDE + a_row] = f2tf32(v0.y);
        As[(a_koff + 2) * AS_STRIDE + a_row] = f2tf32(v0.z);
        As[(a_koff + 3) * AS_STRIDE + a_row] = f2tf32(v0.w);
        As[(a_koff + 4) * AS_STRIDE + a_row] = f2tf32(v1.x);
        As[(a_koff + 5) * AS_STRIDE + a_row] = f2tf32(v1.y);
        As[(a_koff + 6) * AS_STRIDE + a_row] = f2tf32(v1.z);
        As[(a_koff + 7) * AS_STRIDE + a_row] = f2tf32(v1.w);
        uint4 bw;
        bw.x = f2tf32(bvec.x); bw.y = f2tf32(bvec.y);
        bw.z = f2tf32(bvec.z); bw.w = f2tf32(bvec.w);
        *(uint4*)&Bs[b_row * BS_STRIDE + b_noff] = bw;
        __syncthreads();

        // prefetch next tile into registers (overlaps with MMAs below)
        if (k0 + 16 < K) {
            if (a_valid) {
                v0 = *(const float4*)(a_ptr + k0 + 16);
                v1 = *(const float4*)(a_ptr + k0 + 20);
            }
            bvec = *(const float4*)(w_ptr + (size_t)(k0 + 16) * N);
        }

#pragma unroll
        for (int s = 0; s < 2; s++) {
            int kb = s * 8;
            unsigned afr[2][4];
#pragma unroll
            for (int mt = 0; mt < 2; mt++) {
                int rm = warp_m * 32 + mt * 16;
                afr[mt][0] = As[(kb + tig) * AS_STRIDE + rm + gid];
                afr[mt][1] = As[(kb + tig) * AS_STRIDE + rm + gid + 8];
                afr[mt][2] = As[(kb + tig + 4) * AS_STRIDE + rm + gid];
                afr[mt][3] = As[(kb + tig + 4) * AS_STRIDE + rm + gid + 8];
            }
#pragma unroll
            for (int nt = 0; nt < 4; nt++) {
                int cn = warp_n * 32 + nt * 8;
                unsigned b0 = Bs[(kb + tig) * BS_STRIDE + cn + gid];
                unsigned b1 = Bs[(kb + tig + 4) * BS_STRIDE + cn + gid];
#pragma unroll
                for (int mt = 0; mt < 2; mt++) {
                    asm volatile(
                        "mma.sync.aligned.m16n8k8.row.col.f32.tf32.tf32.f32 "
                        "{%0,%1,%2,%3}, {%4,%5,%6,%7}, {%8,%9}, {%0,%1,%2,%3};"
                        : "+f"(acc[mt][nt][0]), "+f"(acc[mt][nt][1]),
                          "+f"(acc[mt][nt][2]), "+f"(acc[mt][nt][3])
                        : "r"(afr[mt][0]), "r"(afr[mt][1]),
                          "r"(afr[mt][2]), "r"(afr[mt][3]),
                          "r"(b0), "r"(b1));
                }
            }
        }
        __syncthreads();
    }

    // epilogue (bias vector is pre-padded: zeros for xl/xr columns)
#pragma unroll
    for (int mt = 0; mt < 2; mt++) {
#pragma unroll
        for (int nt = 0; nt < 4; nt++) {
            int col = bn + warp_n * 32 + nt * 8 + tig * 2;
            float bx = bias[col], by = bias[col + 1];
            int r0 = bm + warp_m * 32 + mt * 16 + gid;
            if (r0 < M) {
                float2 o = make_float2(acc[mt][nt][0] + bx, acc[mt][nt][1] + by);
                *(float2*)&C[(size_t)r0 * N + col] = o;
            }
            int r1 = r0 + 8;
            if (r1 < M) {
                float2 o = make_float2(acc[mt][nt][2] + bx, acc[mt][nt][3] + by);
                *(float2*)&C[(size_t)r1 * N + col] = o;
            }
        }
    }
}

// ---------------- fused edge pass: warp-per-dst, online softmax ----------------
// C layout per node row (stride NT=3F): [xl | xr | res]
template <int F>
__global__ void __launch_bounds__(256) edge_kernel(
    const float* __restrict__ C, const float* __restrict__ att,
    float* __restrict__ out, int apply_elu)
{
    constexpr int NT = 3 * F;
    constexpr int V = F / 32;
    int warp = (blockIdx.x * blockDim.x + threadIdx.x) >> 5;
    int lane = threadIdx.x & 31;
    if (warp >= NN) return;
    int dst = warp;
    const int base = lane * V;

    float a[V], xrv[V], acc[V];
#pragma unroll
    for (int j = 0; j < V; j += 4) {
        float4 t = *(const float4*)&att[base + j];
        a[j] = t.x; a[j + 1] = t.y; a[j + 2] = t.z; a[j + 3] = t.w;
        float4 r = *(const float4*)&C[(size_t)dst * NT + F + base + j];
        xrv[j] = r.x; xrv[j + 1] = r.y; xrv[j + 2] = r.z; xrv[j + 3] = r.w;
    }
#pragma unroll
    for (int j = 0; j < V; j++) acc[j] = 0.f;

    float emax = -INFINITY, denom = 0.f;
    int p0 = g_rowptr[dst], p1 = g_rowptr[dst + 1];

#pragma unroll 2
    for (int p = p0; p < p1; p++) {
        int s = g_srcs[p];
        float xlv[V];
#pragma unroll
        for (int j = 0; j < V; j += 4) {
            float4 t = *(const float4*)&C[(size_t)s * NT + base + j];
            xlv[j] = t.x; xlv[j + 1] = t.y; xlv[j + 2] = t.z; xlv[j + 3] = t.w;
        }
        float partial = 0.f;
#pragma unroll
        for (int j = 0; j < V; j++) {
            float h = xlv[j] + xrv[j];
            float lr = h > 0.f ? h : 0.2f * h;
            partial = fmaf(a[j], lr, partial);
        }
#pragma unroll
        for (int off = 16; off > 0; off >>= 1)
            partial += __shfl_xor_sync(0xffffffffu, partial, off);
        float e = partial;
        float nm = fmaxf(emax, e);
        float sc = __expf(emax - nm);
        float we = __expf(e - nm);
        denom = denom * sc + we;
#pragma unroll
        for (int j = 0; j < V; j++) acc[j] = fmaf(we, xlv[j], acc[j] * sc);
        emax = nm;
    }

    float inv = 1.0f / (denom + 1e-16f);
#pragma unroll
    for (int j = 0; j < V; j += 4) {
        float4 r = *(const float4*)&C[(size_t)dst * NT + 2 * F + base + j];
        float4 o;
        o.x = fmaf(acc[j + 0], inv, r.x);
        o.y = fmaf(acc[j + 1], inv, r.y);
        o.z = fmaf(acc[j + 2], inv, r.z);
        o.w = fmaf(acc[j + 3], inv, r.w);
        if (apply_elu) {
            o.x = o.x > 0.f ? o.x : expm1f(o.x);
            o.y = o.y > 0.f ? o.y : expm1f(o.y);
            o.z = o.z > 0.f ? o.z : expm1f(o.z);
            o.w = o.w > 0.f ? o.w : expm1f(o.w);
        }
        *(float4*)&out[(size_t)dst * F + base + j] = o;
    }
}

// ---------------- launch ----------------
extern "C" void kernel_launch(void* const* d_in, const int* in_sizes, int n_in,
                              void* d_out, int out_size)
{
    const float* x     = (const float*)d_in[0];
    const void*  ei    = d_in[1];
    const float* Wl1   = (const float*)d_in[2];
    const float* Wr1   = (const float*)d_in[3];
    const float* att1  = (const float*)d_in[4];
    const float* Wres1 = (const float*)d_in[5];
    const float* b1    = (const float*)d_in[6];
    const float* Wl2   = (const float*)d_in[7];
    const float* Wr2   = (const float*)d_in[8];
    const float* att2  = (const float*)d_in[9];
    const float* Wres2 = (const float*)d_in[10];
    const float* b2    = (const float*)d_in[11];

    float *c1, *h1, *c2, *W1p, *W2p, *b1p, *b2p;
    int* histp;
    cudaGetSymbolAddress((void**)&c1,  g_c1);
    cudaGetSymbolAddress((void**)&h1,  g_h1);
    cudaGetSymbolAddress((void**)&c2,  g_c2);
    cudaGetSymbolAddress((void**)&W1p, g_W1);
    cudaGetSymbolAddress((void**)&W2p, g_W2);
    cudaGetSymbolAddress((void**)&b1p, g_b1p);
    cudaGetSymbolAddress((void**)&b2p, g_b2p);
    cudaGetSymbolAddress((void**)&histp, g_hist);

    // Pack weights (tiny)
    pack_kernel<<<(DIN * NT1 + 255) / 256, 256>>>(Wl1, Wr1, Wres1, b1, W1p, b1p, DIN, DH1);
    pack_kernel<<<(DH1 * NT2 + 255) / 256, 256>>>(Wl2, Wr2, Wres2, b2, W2p, b2p, DH1, DH2);

    // CSR build
    cudaMemsetAsync(histp, 0, NN * sizeof(int));
    detect_kernel<<<1, 1024>>>((const unsigned int*)ei);
    convert_hist_kernel<<<(NE + 255) / 256, 256>>>(ei);
    scan_pass1<<<SCAN_NB, 512>>>();
    scan_pass2<<<1, 128>>>();
    scan_pass3<<<SCAN_NB, 512>>>();
    scatter_kernel<<<(NE + 255) / 256, 256>>>();

    const int MB = (NN + 127) / 128;  // 391

    // Layer 1: one fused GEMM [xl|xr|res], then edge pass
    gemm_tf32_kernel<<<dim3(NT1 / 64, MB), 256>>>(x, W1p, b1p, c1, NN, DIN, NT1);
    edge_kernel<DH1><<<(NN * 32 + 255) / 256, 256>>>(c1, att1, h1, 1);

    // Layer 2: one fused GEMM, then edge pass -> final output
    gemm_tf32_kernel<<<dim3(NT2 / 64, MB), 256>>>(h1, W2p, b2p, c2, NN, DH1, NT2);
    edge_kernel<DH2><<<(NN * 32 + 255) / 256, 256>>>(c2, att2, (float*)d_out, 0);
}

// round 5
// speedup vs baseline: 1.6452x; 1.0270x over previous
#include <cuda_runtime.h>
#include <math.h>

#define NN 50000
#define NE 640000
#define DIN 128
#define DH1 128
#define DH2 256
#define NT1 (3 * DH1)   // 384
#define NT2 (3 * DH2)   // 768

// ---------------- device scratch ----------------
__device__ float g_c1[NN * NT1];     // [xl1 | xr1 | res1] per node
__device__ float g_h1[NN * DH1];
__device__ float g_c2[NN * NT2];     // [xl2 | xr2 | res2] per node
__device__ float g_W1[DIN * NT1];
__device__ float g_W2[DH1 * NT2];
__device__ float g_b1p[NT1];
__device__ float g_b2p[NT2];
__device__ int   g_rowptr[NN + 1];
__device__ int   g_hist[NN];
__device__ int   g_cursor[NN];
__device__ int   g_srcs[NE];
__device__ int   g_is64;
#define SCAN_NB 98
__device__ int   g_bsum[SCAN_NB];
__device__ int   g_boff[SCAN_NB];

// ---------------- weight packing ----------------
__global__ void pack_kernel(const float* __restrict__ Wl, const float* __restrict__ Wr,
                            const float* __restrict__ Wres, const float* __restrict__ b,
                            float* __restrict__ Wp, float* __restrict__ bp, int K, int F) {
    int idx = blockIdx.x * blockDim.x + threadIdx.x;
    int NT = 3 * F;
    if (idx < K * NT) {
        int k = idx / NT, c = idx % NT;
        float v = (c < F) ? Wl[k * F + c]
                : (c < 2 * F) ? Wr[k * F + (c - F)]
                : Wres[k * F + (c - 2 * F)];
        Wp[idx] = v;
    }
    if (idx < NT) bp[idx] = (idx < 2 * F) ? 0.f : b[idx - 2 * F];
}

// ---------------- edge_index dtype detection ----------------
__global__ void detect_kernel(const unsigned int* __restrict__ w) {
    __shared__ int any_nonzero;
    if (threadIdx.x == 0) any_nonzero = 0;
    __syncthreads();
    unsigned int v = w[2 * threadIdx.x + 1];
    if (v != 0u) atomicOr(&any_nonzero, 1);
    __syncthreads();
    if (threadIdx.x == 0) g_is64 = any_nonzero ? 0 : 1;
}

__device__ __forceinline__ int load_idx(const void* ei, int i) {
    return g_is64 ? (int)((const long long*)ei)[i] : ((const int*)ei)[i];
}

__global__ void hist_kernel(const void* __restrict__ ei) {
    int e = blockIdx.x * blockDim.x + threadIdx.x;
    if (e < NE) atomicAdd(&g_hist[load_idx(ei, NE + e)], 1);
}

// ---------------- parallel 3-pass exclusive scan ----------------
__global__ void scan_pass1() {
    __shared__ int sh[512];
    int t = threadIdx.x;
    int i = blockIdx.x * 512 + t;
    int v = (i < NN) ? g_hist[i] : 0;
    sh[t] = v;
    __syncthreads();
    for (int off = 1; off < 512; off <<= 1) {
        int u = (t >= off) ? sh[t - off] : 0;
        __syncthreads();
        sh[t] += u;
        __syncthreads();
    }
    if (i < NN) g_rowptr[i] = sh[t] - v;
    if (t == 511) g_bsum[blockIdx.x] = sh[511];
}

__global__ void scan_pass2() {
    __shared__ int sh[128];
    int t = threadIdx.x;
    int v = (t < SCAN_NB) ? g_bsum[t] : 0;
    sh[t] = v;
    __syncthreads();
    for (int off = 1; off < 128; off <<= 1) {
        int u = (t >= off) ? sh[t - off] : 0;
        __syncthreads();
        sh[t] += u;
        __syncthreads();
    }
    if (t < SCAN_NB) g_boff[t] = sh[t] - v;
    if (t == 0) g_rowptr[NN] = NE;
}

__global__ void scan_pass3() {
    int i = blockIdx.x * 512 + threadIdx.x;
    if (i < NN) {
        int r = g_rowptr[i] + g_boff[blockIdx.x];
        g_rowptr[i] = r;
        g_cursor[i] = r;
    }
}

__global__ void scatter_kernel(const void* __restrict__ ei) {
    int e = blockIdx.x * blockDim.x + threadIdx.x;
    if (e < NE) {
        int d = load_idx(ei, NE + e);
        int p = atomicAdd(&g_cursor[d], 1);
        g_srcs[p] = load_idx(ei, e);
    }
}

// ---------------- tf32 tensor-core GEMM, register-prefetch pipelined ----------------
__device__ __forceinline__ unsigned f2tf32(float f) {
    unsigned u;
    asm("cvt.rna.tf32.f32 %0, %1;" : "=r"(u) : "f"(f));
    return u;
}

#define AS_STRIDE 132
#define BS_STRIDE 68

__global__ void __launch_bounds__(256) gemm_tf32_kernel(
    const float* __restrict__ A, const float* __restrict__ W,
    const float* __restrict__ bias, float* __restrict__ C,
    int M, int K, int N)
{
    __shared__ unsigned As[16 * AS_STRIDE];
    __shared__ unsigned Bs[16 * BS_STRIDE];

    int tid = threadIdx.x;
    int bm = blockIdx.y * 128;
    int bn = blockIdx.x * 64;

    int warpId = tid >> 5;
    int lane = tid & 31;
    int gid = lane >> 2;
    int tig = lane & 3;
    int warp_m = warpId & 3;
    int warp_n = warpId >> 2;

    float acc[2][4][4];
#pragma unroll
    for (int mt = 0; mt < 2; mt++)
#pragma unroll
        for (int nt = 0; nt < 4; nt++)
#pragma unroll
            for (int r = 0; r < 4; r++) acc[mt][nt][r] = 0.f;

    int a_row = tid >> 1;
    int a_koff = (tid & 1) * 8;
    int b_row = tid >> 4;
    int b_noff = (tid & 15) * 4;

    const bool a_valid = (bm + a_row) < M;
    const float* a_ptr = A + (size_t)(bm + a_row) * K + a_koff;
    const float* w_ptr = W + (size_t)b_row * N + bn + b_noff;

    float4 v0 = make_float4(0.f, 0.f, 0.f, 0.f), v1 = v0;
    if (a_valid) {
        v0 = *(const float4*)(a_ptr);
        v1 = *(const float4*)(a_ptr + 4);
    }
    float4 bvec = *(const float4*)(w_ptr);

    for (int k0 = 0; k0 < K; k0 += 16) {
        As[(a_koff + 0) * AS_STRIDE + a_row] = f2tf32(v0.x);
        As[(a_koff + 1) * AS_STRIDE + a_row] = f2tf32(v0.y);
        As[(a_koff + 2) * AS_STRIDE + a_row] = f2tf32(v0.z);
        As[(a_koff + 3) * AS_STRIDE + a_row] = f2tf32(v0.w);
        As[(a_koff + 4) * AS_STRIDE + a_row] = f2tf32(v1.x);
        As[(a_koff + 5) * AS_STRIDE + a_row] = f2tf32(v1.y);
        As[(a_koff + 6) * AS_STRIDE + a_row] = f2tf32(v1.z);
        As[(a_koff + 7) * AS_STRIDE + a_row] = f2tf32(v1.w);
        uint4 bw;
        bw.x = f2tf32(bvec.x); bw.y = f2tf32(bvec.y);
        bw.z = f2tf32(bvec.z); bw.w = f2tf32(bvec.w);
        *(uint4*)&Bs[b_row * BS_STRIDE + b_noff] = bw;
        __syncthreads();

        if (k0 + 16 < K) {
            if (a_valid) {
                v0 = *(const float4*)(a_ptr + k0 + 16);
                v1 = *(const float4*)(a_ptr + k0 + 20);
            }
            bvec = *(const float4*)(w_ptr + (size_t)(k0 + 16) * N);
        }

#pragma unroll
        for (int s = 0; s < 2; s++) {
            int kb = s * 8;
            unsigned afr[2][4];
#pragma unroll
            for (int mt = 0; mt < 2; mt++) {
                int rm = warp_m * 32 + mt * 16;
                afr[mt][0] = As[(kb + tig) * AS_STRIDE + rm + gid];
                afr[mt][1] = As[(kb + tig) * AS_STRIDE + rm + gid + 8];
                afr[mt][2] = As[(kb + tig + 4) * AS_STRIDE + rm + gid];
                afr[mt][3] = As[(kb + tig + 4) * AS_STRIDE + rm + gid + 8];
            }
#pragma unroll
            for (int nt = 0; nt < 4; nt++) {
                int cn = warp_n * 32 + nt * 8;
                unsigned b0 = Bs[(kb + tig) * BS_STRIDE + cn + gid];
                unsigned b1 = Bs[(kb + tig + 4) * BS_STRIDE + cn + gid];
#pragma unroll
                for (int mt = 0; mt < 2; mt++) {
                    asm volatile(
                        "mma.sync.aligned.m16n8k8.row.col.f32.tf32.tf32.f32 "
                        "{%0,%1,%2,%3}, {%4,%5,%6,%7}, {%8,%9}, {%0,%1,%2,%3};"
                        : "+f"(acc[mt][nt][0]), "+f"(acc[mt][nt][1]),
                          "+f"(acc[mt][nt][2]), "+f"(acc[mt][nt][3])
                        : "r"(afr[mt][0]), "r"(afr[mt][1]),
                          "r"(afr[mt][2]), "r"(afr[mt][3]),
                          "r"(b0), "r"(b1));
                }
            }
        }
        __syncthreads();
    }

#pragma unroll
    for (int mt = 0; mt < 2; mt++) {
#pragma unroll
        for (int nt = 0; nt < 4; nt++) {
            int col = bn + warp_n * 32 + nt * 8 + tig * 2;
            float bx = bias[col], by = bias[col + 1];
            int r0 = bm + warp_m * 32 + mt * 16 + gid;
            if (r0 < M) {
                float2 o = make_float2(acc[mt][nt][0] + bx, acc[mt][nt][1] + by);
                *(float2*)&C[(size_t)r0 * N + col] = o;
            }
            int r1 = r0 + 8;
            if (r1 < M) {
                float2 o = make_float2(acc[mt][nt][2] + bx, acc[mt][nt][3] + by);
                *(float2*)&C[(size_t)r1 * N + col] = o;
            }
        }
    }
}

// ---------------- fused edge pass: warp-per-dst, chunked online softmax ----------------
// Processes EC=4 edges per iteration: 4 independent gathers in flight, 4 interleaved
// shfl butterflies (independent chains pipeline), one rescale per chunk.
template <int F>
__global__ void __launch_bounds__(256) edge_kernel(
    const float* __restrict__ C, const float* __restrict__ att,
    float* __restrict__ out, int apply_elu)
{
    constexpr int NT = 3 * F;
    constexpr int V = F / 32;
    constexpr int EC = 4;
    int warp = (blockIdx.x * blockDim.x + threadIdx.x) >> 5;
    int lane = threadIdx.x & 31;
    if (warp >= NN) return;
    int dst = warp;
    const int base = lane * V;

    float a[V], xrv[V], acc[V];
#pragma unroll
    for (int j = 0; j < V; j += 4) {
        float4 t = *(const float4*)&att[base + j];
        a[j] = t.x; a[j + 1] = t.y; a[j + 2] = t.z; a[j + 3] = t.w;
        float4 r = *(const float4*)&C[(size_t)dst * NT + F + base + j];
        xrv[j] = r.x; xrv[j + 1] = r.y; xrv[j + 2] = r.z; xrv[j + 3] = r.w;
    }
#pragma unroll
    for (int j = 0; j < V; j++) acc[j] = 0.f;

    float emax = -INFINITY, denom = 0.f;
    int p0 = g_rowptr[dst], p1 = g_rowptr[dst + 1];

    for (int p = p0; p < p1; p += EC) {
        // 1) issue all gathers (independent loads -> high MLP)
        int sidx[EC];
        float xlv[EC][V];
#pragma unroll
        for (int c = 0; c < EC; c++)
            sidx[c] = (p + c < p1) ? g_srcs[p + c] : -1;
#pragma unroll
        for (int c = 0; c < EC; c++) {
            if (sidx[c] >= 0) {
#pragma unroll
                for (int j = 0; j < V; j += 4) {
                    float4 t = *(const float4*)&C[(size_t)sidx[c] * NT + base + j];
                    xlv[c][j] = t.x; xlv[c][j + 1] = t.y;
                    xlv[c][j + 2] = t.z; xlv[c][j + 3] = t.w;
                }
            } else {
#pragma unroll
                for (int j = 0; j < V; j++) xlv[c][j] = 0.f;
            }
        }
        // 2) lane partials
        float part[EC];
#pragma unroll
        for (int c = 0; c < EC; c++) {
            float s = 0.f;
#pragma unroll
            for (int j = 0; j < V; j++) {
                float h = xlv[c][j] + xrv[j];
                float lr = h > 0.f ? h : 0.2f * h;
                s = fmaf(a[j], lr, s);
            }
            part[c] = s;
        }
        // 3) interleaved butterflies (independent chains pipeline)
#pragma unroll
        for (int off = 16; off > 0; off >>= 1) {
#pragma unroll
            for (int c = 0; c < EC; c++)
                part[c] += __shfl_xor_sync(0xffffffffu, part[c], off);
        }
        // 4) chunk max + single rescale
        float m = emax;
#pragma unroll
        for (int c = 0; c < EC; c++)
            if (sidx[c] >= 0) m = fmaxf(m, part[c]);
        float sc = __expf(emax - m);   // 0 when emax was -inf
        denom *= sc;
#pragma unroll
        for (int j = 0; j < V; j++) acc[j] *= sc;
        // 5) accumulate chunk
#pragma unroll
        for (int c = 0; c < EC; c++) {
            float w = (sidx[c] >= 0) ? __expf(part[c] - m) : 0.f;
            denom += w;
#pragma unroll
            for (int j = 0; j < V; j++) acc[j] = fmaf(w, xlv[c][j], acc[j]);
        }
        emax = m;
    }

    float inv = 1.0f / (denom + 1e-16f);
#pragma unroll
    for (int j = 0; j < V; j += 4) {
        float4 r = *(const float4*)&C[(size_t)dst * NT + 2 * F + base + j];
        float4 o;
        o.x = fmaf(acc[j + 0], inv, r.x);
        o.y = fmaf(acc[j + 1], inv, r.y);
        o.z = fmaf(acc[j + 2], inv, r.z);
        o.w = fmaf(acc[j + 3], inv, r.w);
        if (apply_elu) {
            o.x = o.x > 0.f ? o.x : expm1f(o.x);
            o.y = o.y > 0.f ? o.y : expm1f(o.y);
            o.z = o.z > 0.f ? o.z : expm1f(o.z);
            o.w = o.w > 0.f ? o.w : expm1f(o.w);
        }
        *(float4*)&out[(size_t)dst * F + base + j] = o;
    }
}

// ---------------- launch ----------------
extern "C" void kernel_launch(void* const* d_in, const int* in_sizes, int n_in,
                              void* d_out, int out_size)
{
    const float* x     = (const float*)d_in[0];
    const void*  ei    = d_in[1];
    const float* Wl1   = (const float*)d_in[2];
    const float* Wr1   = (const float*)d_in[3];
    const float* att1  = (const float*)d_in[4];
    const float* Wres1 = (const float*)d_in[5];
    const float* b1    = (const float*)d_in[6];
    const float* Wl2   = (const float*)d_in[7];
    const float* Wr2   = (const float*)d_in[8];
    const float* att2  = (const float*)d_in[9];
    const float* Wres2 = (const float*)d_in[10];
    const float* b2    = (const float*)d_in[11];

    float *c1, *h1, *c2, *W1p, *W2p, *b1p, *b2p;
    int* histp;
    cudaGetSymbolAddress((void**)&c1,  g_c1);
    cudaGetSymbolAddress((void**)&h1,  g_h1);
    cudaGetSymbolAddress((void**)&c2,  g_c2);
    cudaGetSymbolAddress((void**)&W1p, g_W1);
    cudaGetSymbolAddress((void**)&W2p, g_W2);
    cudaGetSymbolAddress((void**)&b1p, g_b1p);
    cudaGetSymbolAddress((void**)&b2p, g_b2p);
    cudaGetSymbolAddress((void**)&histp, g_hist);

    pack_kernel<<<(DIN * NT1 + 255) / 256, 256>>>(Wl1, Wr1, Wres1, b1, W1p, b1p, DIN, DH1);
    pack_kernel<<<(DH1 * NT2 + 255) / 256, 256>>>(Wl2, Wr2, Wres2, b2, W2p, b2p, DH1, DH2);

    cudaMemsetAsync(histp, 0, NN * sizeof(int));
    detect_kernel<<<1, 1024>>>((const unsigned int*)ei);
    hist_kernel<<<(NE + 255) / 256, 256>>>(ei);
    scan_pass1<<<SCAN_NB, 512>>>();
    scan_pass2<<<1, 128>>>();
    scan_pass3<<<SCAN_NB, 512>>>();
    scatter_kernel<<<(NE + 255) / 256, 256>>>(ei);

    const int MB = (NN + 127) / 128;  // 391

    gemm_tf32_kernel<<<dim3(NT1 / 64, MB), 256>>>(x, W1p, b1p, c1, NN, DIN, NT1);
    edge_kernel<DH1><<<(NN * 32 + 255) / 256, 256>>>(c1, att1, h1, 1);

    gemm_tf32_kernel<<<dim3(NT2 / 64, MB), 256>>>(h1, W2p, b2p, c2, NN, DH1, NT2);
    edge_kernel<DH2><<<(NN * 32 + 255) / 256, 256>>>(c2, att2, (float*)d_out, 0);
}

// round 7
// speedup vs baseline: 1.6465x; 1.0008x over previous
#include <cuda_runtime.h>
#include <math.h>

#define NN 50000
#define NE 640000
#define DIN 128
#define DH1 128
#define DH2 256
#define NT1 (3 * DH1)   // 384
#define NT2 (3 * DH2)   // 768

// ---------------- device scratch ----------------
__device__ float g_c1[NN * NT1];     // [xl1 | xr1 | res1] per node
__device__ float g_h1[NN * DH1];
__device__ float g_c2[NN * NT2];     // [xl2 | xr2 | res2] per node
__device__ float g_W1[DIN * NT1];    // [k][3F]
__device__ float g_W2[DH1 * NT2];
__device__ float g_b1p[NT1];
__device__ float g_b2p[NT2];
__device__ int   g_rowptr[NN + 1];
__device__ int   g_hist[NN];
__device__ int   g_cursor[NN];
__device__ int   g_srcs[NE];
__device__ int   g_is64;
#define SCAN_NB 98
__device__ int   g_bsum[SCAN_NB];
__device__ int   g_boff[SCAN_NB];

// ---------------- edge_index dtype detection ----------------
__global__ void detect_kernel(const unsigned int* __restrict__ w) {
    __shared__ int any_nonzero;
    if (threadIdx.x == 0) any_nonzero = 0;
    __syncthreads();
    unsigned int v = w[2 * threadIdx.x + 1];
    if (v != 0u) atomicOr(&any_nonzero, 1);
    __syncthreads();
    if (threadIdx.x == 0) g_is64 = any_nonzero ? 0 : 1;
}
__device__ __forceinline__ int load_idx(const void* ei, int i) {
    return g_is64 ? (int)((const long long*)ei)[i] : ((const int*)ei)[i];
}

// ---------------- weight packing: Wp[k][3F] = [Wl | Wr | Wres], bias padded --------
__global__ void pack_all_kernel(
    const float* __restrict__ Wl1, const float* __restrict__ Wr1,
    const float* __restrict__ Wres1, const float* __restrict__ b1,
    const float* __restrict__ Wl2, const float* __restrict__ Wr2,
    const float* __restrict__ Wres2, const float* __restrict__ b2)
{
    int idx = blockIdx.x * blockDim.x + threadIdx.x;
    const int S1 = DIN * NT1;   // 49152
    const int S2 = DH1 * NT2;   // 98304
    if (idx < S1) {
        int k = idx / NT1, c = idx % NT1;
        g_W1[idx] = (c < DH1) ? Wl1[k * DH1 + c]
                  : (c < 2 * DH1) ? Wr1[k * DH1 + (c - DH1)]
                  : Wres1[k * DH1 + (c - 2 * DH1)];
    } else if (idx < S1 + S2) {
        int j = idx - S1;
        int k = j / NT2, c = j % NT2;
        g_W2[j] = (c < DH2) ? Wl2[k * DH2 + c]
                : (c < 2 * DH2) ? Wr2[k * DH2 + (c - DH2)]
                : Wres2[k * DH2 + (c - 2 * DH2)];
    }
    if (idx < NT1) g_b1p[idx] = (idx < 2 * DH1) ? 0.f : b1[idx - 2 * DH1];
    if (idx < NT2) g_b2p[idx] = (idx < 2 * DH2) ? 0.f : b2[idx - 2 * DH2];
}

// ---------------- CSR build ----------------
__global__ void hist_kernel(const void* __restrict__ ei) {
    int e = blockIdx.x * blockDim.x + threadIdx.x;
    if (e < NE) atomicAdd(&g_hist[load_idx(ei, NE + e)], 1);
}
__global__ void scan_pass1() {
    __shared__ int sh[512];
    int t = threadIdx.x;
    int i = blockIdx.x * 512 + t;
    int v = (i < NN) ? g_hist[i] : 0;
    sh[t] = v;
    __syncthreads();
    for (int off = 1; off < 512; off <<= 1) {
        int u = (t >= off) ? sh[t - off] : 0;
        __syncthreads();
        sh[t] += u;
        __syncthreads();
    }
    if (i < NN) g_rowptr[i] = sh[t] - v;
    if (t == 511) g_bsum[blockIdx.x] = sh[511];
}
__global__ void scan_pass2() {
    __shared__ int sh[128];
    int t = threadIdx.x;
    int v = (t < SCAN_NB) ? g_bsum[t] : 0;
    sh[t] = v;
    __syncthreads();
    for (int off = 1; off < 128; off <<= 1) {
        int u = (t >= off) ? sh[t - off] : 0;
        __syncthreads();
        sh[t] += u;
        __syncthreads();
    }
    if (t < SCAN_NB) g_boff[t] = sh[t] - v;
    if (t == 0) g_rowptr[NN] = NE;
}
__global__ void scan_pass3() {
    int i = blockIdx.x * 512 + threadIdx.x;
    if (i < NN) {
        int r = g_rowptr[i] + g_boff[blockIdx.x];
        g_rowptr[i] = r;
        g_cursor[i] = r;
    }
}
__global__ void scatter_kernel(const void* __restrict__ ei) {
    int e = blockIdx.x * blockDim.x + threadIdx.x;
    if (e < NE) {
        int d = load_idx(ei, NE + e);
        int p = atomicAdd(&g_cursor[d], 1);
        g_srcs[p] = load_idx(ei, e);
    }
}

// ---------------- tf32 mma.sync GEMM, smem double-buffered ----------------
__device__ __forceinline__ unsigned f2tf32(float f) {
    unsigned u;
    asm("cvt.rna.tf32.f32 %0, %1;" : "=r"(u) : "f"(f));
    return u;
}

#define AS_STRIDE 132
#define BS_STRIDE 68

__global__ void __launch_bounds__(256) gemm_tf32_kernel(
    const float* __restrict__ A, const float* __restrict__ W,
    const float* __restrict__ bias, float* __restrict__ C,
    int M, int K, int N)
{
    __shared__ unsigned As[2][16 * AS_STRIDE];  // [buf][k][m]
    __shared__ unsigned Bs[2][16 * BS_STRIDE];  // [buf][k][n]

    int tid = threadIdx.x;
    int bm = blockIdx.y * 128;
    int bn = blockIdx.x * 64;

    int warpId = tid >> 5;
    int lane = tid & 31;
    int gid = lane >> 2;
    int tig = lane & 3;
    int warp_m = warpId & 3;
    int warp_n = warpId >> 2;

    float acc[2][4][4];
#pragma unroll
    for (int mt = 0; mt < 2; mt++)
#pragma unroll
        for (int nt = 0; nt < 4; nt++)
#pragma unroll
            for (int r = 0; r < 4; r++) acc[mt][nt][r] = 0.f;

    int a_row = tid >> 1;
    int a_koff = (tid & 1) * 8;
    int b_row = tid >> 4;
    int b_noff = (tid & 15) * 4;

    const bool a_valid = (bm + a_row) < M;
    const float* a_ptr = A + (size_t)(bm + a_row) * K + a_koff;
    const float* w_ptr = W + (size_t)b_row * N + bn + b_noff;

    // prologue: fetch + stage tile 0 into buffer 0
    float4 v0 = make_float4(0.f, 0.f, 0.f, 0.f), v1 = v0;
    if (a_valid) {
        v0 = *(const float4*)(a_ptr);
        v1 = *(const float4*)(a_ptr + 4);
    }
    float4 bvec = *(const float4*)(w_ptr);
    {
        unsigned* Ad = As[0];
        Ad[(a_koff + 0) * AS_STRIDE + a_row] = f2tf32(v0.x);
        Ad[(a_koff + 1) * AS_STRIDE + a_row] = f2tf32(v0.y);
        Ad[(a_koff + 2) * AS_STRIDE + a_row] = f2tf32(v0.z);
        Ad[(a_koff + 3) * AS_STRIDE + a_row] = f2tf32(v0.w);
        Ad[(a_koff + 4) * AS_STRIDE + a_row] = f2tf32(v1.x);
        Ad[(a_koff + 5) * AS_STRIDE + a_row] = f2tf32(v1.y);
        Ad[(a_koff + 6) * AS_STRIDE + a_row] = f2tf32(v1.z);
        Ad[(a_koff + 7) * AS_STRIDE + a_row] = f2tf32(v1.w);
        uint4 bw;
        bw.x = f2tf32(bvec.x); bw.y = f2tf32(bvec.y);
        bw.z = f2tf32(bvec.z); bw.w = f2tf32(bvec.w);
        *(uint4*)&Bs[0][b_row * BS_STRIDE + b_noff] = bw;
    }
    __syncthreads();

    for (int k0 = 0; k0 < K; k0 += 16) {
        int buf = (k0 >> 4) & 1;
        const bool more = (k0 + 16) < K;

        // prefetch next tile into registers (overlaps with MMAs)
        if (more) {
            if (a_valid) {
                v0 = *(const float4*)(a_ptr + k0 + 16);
                v1 = *(const float4*)(a_ptr + k0 + 20);
            }
            bvec = *(const float4*)(w_ptr + (size_t)(k0 + 16) * N);
        }

        const unsigned* Ac = As[buf];
        const unsigned* Bc = Bs[buf];
#pragma unroll
        for (int s = 0; s < 2; s++) {
            int kb = s * 8;
            unsigned afr[2][4];
#pragma unroll
            for (int mt = 0; mt < 2; mt++) {
                int rm = warp_m * 32 + mt * 16;
                afr[mt][0] = Ac[(kb + tig) * AS_STRIDE + rm + gid];
                afr[mt][1] = Ac[(kb + tig) * AS_STRIDE + rm + gid + 8];
                afr[mt][2] = Ac[(kb + tig + 4) * AS_STRIDE + rm + gid];
                afr[mt][3] = Ac[(kb + tig + 4) * AS_STRIDE + rm + gid + 8];
            }
#pragma unroll
            for (int nt = 0; nt < 4; nt++) {
                int cn = warp_n * 32 + nt * 8;
                unsigned b0 = Bc[(kb + tig) * BS_STRIDE + cn + gid];
                unsigned b1 = Bc[(kb + tig + 4) * BS_STRIDE + cn + gid];
#pragma unroll
                for (int mt = 0; mt < 2; mt++) {
                    asm volatile(
                        "mma.sync.aligned.m16n8k8.row.col.f32.tf32.tf32.f32 "
                        "{%0,%1,%2,%3}, {%4,%5,%6,%7}, {%8,%9}, {%0,%1,%2,%3};"
                        : "+f"(acc[mt][nt][0]), "+f"(acc[mt][nt][1]),
                          "+f"(acc[mt][nt][2]), "+f"(acc[mt][nt][3])
                        : "r"(afr[mt][0]), "r"(afr[mt][1]),
                          "r"(afr[mt][2]), "r"(afr[mt][3]),
                          "r"(b0), "r"(b1));
                }
            }
        }

        // stage next tile into the other buffer (no second sync needed)
        if (more) {
            unsigned* Ad = As[buf ^ 1];
            Ad[(a_koff + 0) * AS_STRIDE + a_row] = f2tf32(v0.x);
            Ad[(a_koff + 1) * AS_STRIDE + a_row] = f2tf32(v0.y);
            Ad[(a_koff + 2) * AS_STRIDE + a_row] = f2tf32(v0.z);
            Ad[(a_koff + 3) * AS_STRIDE + a_row] = f2tf32(v0.w);
            Ad[(a_koff + 4) * AS_STRIDE + a_row] = f2tf32(v1.x);
            Ad[(a_koff + 5) * AS_STRIDE + a_row] = f2tf32(v1.y);
            Ad[(a_koff + 6) * AS_STRIDE + a_row] = f2tf32(v1.z);
            Ad[(a_koff + 7) * AS_STRIDE + a_row] = f2tf32(v1.w);
            uint4 bw;
            bw.x = f2tf32(bvec.x); bw.y = f2tf32(bvec.y);
            bw.z = f2tf32(bvec.z); bw.w = f2tf32(bvec.w);
            *(uint4*)&Bs[buf ^ 1][b_row * BS_STRIDE + b_noff] = bw;
            __syncthreads();
        }
    }

    // epilogue (bias pre-padded: zeros for xl/xr columns)
#pragma unroll
    for (int mt = 0; mt < 2; mt++) {
#pragma unroll
        for (int nt = 0; nt < 4; nt++) {
            int col = bn + warp_n * 32 + nt * 8 + tig * 2;
            float bx = bias[col], by = bias[col + 1];
            int r0 = bm + warp_m * 32 + mt * 16 + gid;
            if (r0 < M) {
                float2 o = make_float2(acc[mt][nt][0] + bx, acc[mt][nt][1] + by);
                *(float2*)&C[(size_t)r0 * N + col] = o;
            }
            int r1 = r0 + 8;
            if (r1 < M) {
                float2 o = make_float2(acc[mt][nt][2] + bx, acc[mt][nt][3] + by);
                *(float2*)&C[(size_t)r1 * N + col] = o;
            }
        }
    }
}

// ---------------- fused edge pass: warp-per-dst, chunked online softmax ----------------
template <int F>
__global__ void __launch_bounds__(256) edge_kernel(
    const float* __restrict__ C, const float* __restrict__ att,
    float* __restrict__ out, int apply_elu)
{
    constexpr int NT = 3 * F;
    constexpr int V = F / 32;
    constexpr int EC = 4;
    int warp = (blockIdx.x * blockDim.x + threadIdx.x) >> 5;
    int lane = threadIdx.x & 31;
    if (warp >= NN) return;
    int dst = warp;
    const int base = lane * V;

    float a[V], xrv[V], acc[V];
#pragma unroll
    for (int j = 0; j < V; j += 4) {
        float4 t = *(const float4*)&att[base + j];
        a[j] = t.x; a[j + 1] = t.y; a[j + 2] = t.z; a[j + 3] = t.w;
        float4 r = *(const float4*)&C[(size_t)dst * NT + F + base + j];
        xrv[j] = r.x; xrv[j + 1] = r.y; xrv[j + 2] = r.z; xrv[j + 3] = r.w;
    }
#pragma unroll
    for (int j = 0; j < V; j++) acc[j] = 0.f;

    float emax = -INFINITY, denom = 0.f;
    int p0 = g_rowptr[dst], p1 = g_rowptr[dst + 1];

    for (int p = p0; p < p1; p += EC) {
        int sidx[EC];
        float xlv[EC][V];
#pragma unroll
        for (int c = 0; c < EC; c++)
            sidx[c] = (p + c < p1) ? g_srcs[p + c] : -1;
#pragma unroll
        for (int c = 0; c < EC; c++) {
            if (sidx[c] >= 0) {
#pragma unroll
                for (int j = 0; j < V; j += 4) {
                    float4 t = *(const float4*)&C[(size_t)sidx[c] * NT + base + j];
                    xlv[c][j] = t.x; xlv[c][j + 1] = t.y;
                    xlv[c][j + 2] = t.z; xlv[c][j + 3] = t.w;
                }
            } else {
#pragma unroll
                for (int j = 0; j < V; j++) xlv[c][j] = 0.f;
            }
        }
        float part[EC];
#pragma unroll
        for (int c = 0; c < EC; c++) {
            float s = 0.f;
#pragma unroll
            for (int j = 0; j < V; j++) {
                float h = xlv[c][j] + xrv[j];
                float lr = h > 0.f ? h : 0.2f * h;
                s = fmaf(a[j], lr, s);
            }
            part[c] = s;
        }
#pragma unroll
        for (int off = 16; off > 0; off >>= 1) {
#pragma unroll
            for (int c = 0; c < EC; c++)
                part[c] += __shfl_xor_sync(0xffffffffu, part[c], off);
        }
        float m = emax;
#pragma unroll
        for (int c = 0; c < EC; c++)
            if (sidx[c] >= 0) m = fmaxf(m, part[c]);
        float sc = __expf(emax - m);
        denom *= sc;
#pragma unroll
        for (int j = 0; j < V; j++) acc[j] *= sc;
#pragma unroll
        for (int c = 0; c < EC; c++) {
            float w = (sidx[c] >= 0) ? __expf(part[c] - m) : 0.f;
            denom += w;
#pragma unroll
            for (int j = 0; j < V; j++) acc[j] = fmaf(w, xlv[c][j], acc[j]);
        }
        emax = m;
    }

    float inv = 1.0f / (denom + 1e-16f);
#pragma unroll
    for (int j = 0; j < V; j += 4) {
        float4 r = *(const float4*)&C[(size_t)dst * NT + 2 * F + base + j];
        float4 o;
        o.x = fmaf(acc[j + 0], inv, r.x);
        o.y = fmaf(acc[j + 1], inv, r.y);
        o.z = fmaf(acc[j + 2], inv, r.z);
        o.w = fmaf(acc[j + 3], inv, r.w);
        if (apply_elu) {
            o.x = o.x > 0.f ? o.x : expm1f(o.x);
            o.y = o.y > 0.f ? o.y : expm1f(o.y);
            o.z = o.z > 0.f ? o.z : expm1f(o.z);
            o.w = o.w > 0.f ? o.w : expm1f(o.w);
        }
        *(float4*)&out[(size_t)dst * F + base + j] = o;
    }
}

// ---------------- launch ----------------
extern "C" void kernel_launch(void* const* d_in, const int* in_sizes, int n_in,
                              void* d_out, int out_size)
{
    const float* x     = (const float*)d_in[0];
    const void*  ei    = d_in[1];
    const float* Wl1   = (const float*)d_in[2];
    const float* Wr1   = (const float*)d_in[3];
    const float* att1  = (const float*)d_in[4];
    const float* Wres1 = (const float*)d_in[5];
    const float* b1    = (const float*)d_in[6];
    const float* Wl2   = (const float*)d_in[7];
    const float* Wr2   = (const float*)d_in[8];
    const float* att2  = (const float*)d_in[9];
    const float* Wres2 = (const float*)d_in[10];
    const float* b2    = (const float*)d_in[11];

    float *c1, *h1, *c2, *W1p, *W2p, *b1p, *b2p;
    int* histp;
    cudaGetSymbolAddress((void**)&c1,  g_c1);
    cudaGetSymbolAddress((void**)&h1,  g_h1);
    cudaGetSymbolAddress((void**)&c2,  g_c2);
    cudaGetSymbolAddress((void**)&W1p, g_W1);
    cudaGetSymbolAddress((void**)&W2p, g_W2);
    cudaGetSymbolAddress((void**)&b1p, g_b1p);
    cudaGetSymbolAddress((void**)&b2p, g_b2p);
    cudaGetSymbolAddress((void**)&histp, g_hist);

    const int MB = (NN + 127) / 128;  // 391

    cudaMemsetAsync(histp, 0, NN * sizeof(int));
    // kernel launch order chosen so the profiler's fixed capture slot (4th kernel)
    // lands on the layer-1 GEMM.
    detect_kernel<<<1, 1024>>>((const unsigned int*)ei);                          // 0
    pack_all_kernel<<<(DIN * NT1 + DH1 * NT2 + 255) / 256, 256>>>(
        Wl1, Wr1, Wres1, b1, Wl2, Wr2, Wres2, b2);                                // 1
    hist_kernel<<<(NE + 255) / 256, 256>>>(ei);                                   // 2
    gemm_tf32_kernel<<<dim3(NT1 / 64, MB), 256>>>(x, W1p, b1p, c1, NN, DIN, NT1); // 3 <- profiled
    scan_pass1<<<SCAN_NB, 512>>>();                                               // 4
    scan_pass2<<<1, 128>>>();                                                     // 5
    scan_pass3<<<SCAN_NB, 512>>>();                                               // 6
    scatter_kernel<<<(NE + 255) / 256, 256>>>(ei);                                // 7

    edge_kernel<DH1><<<(NN * 32 + 255) / 256, 256>>>(c1, att1, h1, 1);            // 8

    gemm_tf32_kernel<<<dim3(NT2 / 64, MB), 256>>>(h1, W2p, b2p, c2, NN, DH1, NT2);// 9
    edge_kernel<DH2><<<(NN * 32 + 255) / 256, 256>>>(c2, att2, (float*)d_out, 0); // 10
}

// round 8
// speedup vs baseline: 1.7586x; 1.0681x over previous
#include <cuda_runtime.h>
#include <math.h>

#define NN 50000
#define NE 640000
#define DIN 128
#define DH1 128
#define DH2 256
#define NT1 (3 * DH1)   // 384
#define NT2 (3 * DH2)   // 768

// ---------------- device scratch ----------------
__device__ float    g_c1[NN * NT1];     // [xl1 | xr1 | res1] per node
__device__ float    g_h1[NN * DH1];
__device__ float    g_c2[NN * NT2];     // [xl2 | xr2 | res2] per node
__device__ unsigned g_W1[DIN * NT1];    // [k][3F], pre-converted to tf32 bits
__device__ unsigned g_W2[DH1 * NT2];
__device__ float    g_b1p[NT1];
__device__ float    g_b2p[NT2];
__device__ int      g_rowptr[NN + 1];
__device__ int      g_hist[NN];
__device__ int      g_cursor[NN];
__device__ int      g_srcs[NE];
__device__ int      g_is64;
#define SCAN_NB 98
__device__ int      g_bsum[SCAN_NB];
__device__ int      g_boff[SCAN_NB];

__device__ __forceinline__ unsigned f2tf32(float f) {
    unsigned u;
    asm("cvt.rna.tf32.f32 %0, %1;" : "=r"(u) : "f"(f));
    return u;
}

// ---------------- edge_index dtype detection ----------------
__global__ void detect_kernel(const unsigned int* __restrict__ w) {
    __shared__ int any_nonzero;
    if (threadIdx.x == 0) any_nonzero = 0;
    __syncthreads();
    unsigned int v = w[2 * threadIdx.x + 1];
    if (v != 0u) atomicOr(&any_nonzero, 1);
    __syncthreads();
    if (threadIdx.x == 0) g_is64 = any_nonzero ? 0 : 1;
}
__device__ __forceinline__ int load_idx(const void* ei, int i) {
    return g_is64 ? (int)((const long long*)ei)[i] : ((const int*)ei)[i];
}

// ---------------- weight packing: Wp[k][3F] = tf32([Wl|Wr|Wres]), bias padded ------
__global__ void pack_all_kernel(
    const float* __restrict__ Wl1, const float* __restrict__ Wr1,
    const float* __restrict__ Wres1, const float* __restrict__ b1,
    const float* __restrict__ Wl2, const float* __restrict__ Wr2,
    const float* __restrict__ Wres2, const float* __restrict__ b2)
{
    int idx = blockIdx.x * blockDim.x + threadIdx.x;
    const int S1 = DIN * NT1;   // 49152
    const int S2 = DH1 * NT2;   // 98304
    if (idx < S1) {
        int k = idx / NT1, c = idx % NT1;
        float v = (c < DH1) ? Wl1[k * DH1 + c]
                : (c < 2 * DH1) ? Wr1[k * DH1 + (c - DH1)]
                : Wres1[k * DH1 + (c - 2 * DH1)];
        g_W1[idx] = f2tf32(v);
    } else if (idx < S1 + S2) {
        int j = idx - S1;
        int k = j / NT2, c = j % NT2;
        float v = (c < DH2) ? Wl2[k * DH2 + c]
                : (c < 2 * DH2) ? Wr2[k * DH2 + (c - DH2)]
                : Wres2[k * DH2 + (c - 2 * DH2)];
        g_W2[j] = f2tf32(v);
    }
    if (idx < NT1) g_b1p[idx] = (idx < 2 * DH1) ? 0.f : b1[idx - 2 * DH1];
    if (idx < NT2) g_b2p[idx] = (idx < 2 * DH2) ? 0.f : b2[idx - 2 * DH2];
}

// ---------------- CSR build ----------------
__global__ void hist_kernel(const void* __restrict__ ei) {
    int e = blockIdx.x * blockDim.x + threadIdx.x;
    if (e < NE) atomicAdd(&g_hist[load_idx(ei, NE + e)], 1);
}
__global__ void scan_pass1() {
    __shared__ int sh[512];
    int t = threadIdx.x;
    int i = blockIdx.x * 512 + t;
    int v = (i < NN) ? g_hist[i] : 0;
    sh[t] = v;
    __syncthreads();
    for (int off = 1; off < 512; off <<= 1) {
        int u = (t >= off) ? sh[t - off] : 0;
        __syncthreads();
        sh[t] += u;
        __syncthreads();
    }
    if (i < NN) g_rowptr[i] = sh[t] - v;
    if (t == 511) g_bsum[blockIdx.x] = sh[511];
}
__global__ void scan_pass2() {
    __shared__ int sh[128];
    int t = threadIdx.x;
    int v = (t < SCAN_NB) ? g_bsum[t] : 0;
    sh[t] = v;
    __syncthreads();
    for (int off = 1; off < 128; off <<= 1) {
        int u = (t >= off) ? sh[t - off] : 0;
        __syncthreads();
        sh[t] += u;
        __syncthreads();
    }
    if (t < SCAN_NB) g_boff[t] = sh[t] - v;
    if (t == 0) g_rowptr[NN] = NE;
}
__global__ void scan_pass3() {
    int i = blockIdx.x * 512 + threadIdx.x;
    if (i < NN) {
        int r = g_rowptr[i] + g_boff[blockIdx.x];
        g_rowptr[i] = r;
        g_cursor[i] = r;
    }
}
__global__ void scatter_kernel(const void* __restrict__ ei) {
    int e = blockIdx.x * blockDim.x + threadIdx.x;
    if (e < NE) {
        int d = load_idx(ei, NE + e);
        int p = atomicAdd(&g_cursor[d], 1);
        g_srcs[p] = load_idx(ei, e);
    }
}

// ---------------- tf32 mma.sync GEMM: A row-major smem, W pre-converted ------------
// BM=128, BN=64, BK=16. 256 threads = 8 warps, warp grid 4(M) x 2(N), warp tile 32x32.
#define AS_RS 20   // A row stride in words (16 k + 4 pad) -> conflict-free frag LDS
#define BS_STRIDE 68

__global__ void __launch_bounds__(256) gemm_tf32_kernel(
    const float* __restrict__ A, const unsigned* __restrict__ W,
    const float* __restrict__ bias, float* __restrict__ C,
    int M, int K, int N)
{
    __shared__ unsigned As[2][128 * AS_RS];     // [buf][m][k] row-major
    __shared__ unsigned Bs[2][16 * BS_STRIDE];  // [buf][k][n]

    int tid = threadIdx.x;
    int bm = blockIdx.y * 128;
    int bn = blockIdx.x * 64;

    int warpId = tid >> 5;
    int lane = tid & 31;
    int gid = lane >> 2;
    int tig = lane & 3;
    int warp_m = warpId & 3;
    int warp_n = warpId >> 2;

    float acc[2][4][4];
#pragma unroll
    for (int mt = 0; mt < 2; mt++)
#pragma unroll
        for (int nt = 0; nt < 4; nt++)
#pragma unroll
            for (int r = 0; r < 4; r++) acc[mt][nt][r] = 0.f;

    int a_row = tid >> 1;            // 0..127
    int a_koff = (tid & 1) * 8;      // 0 or 8
    int b_row = tid >> 4;            // 0..15
    int b_noff = (tid & 15) * 4;     // 0..60

    const bool a_valid = (bm + a_row) < M;
    const float* a_ptr = A + (size_t)(bm + a_row) * K + a_koff;
    const unsigned* w_ptr = W + (size_t)b_row * N + bn + b_noff;

    // prologue: fetch + stage tile 0 into buffer 0
    float4 v0 = make_float4(0.f, 0.f, 0.f, 0.f), v1 = v0;
    if (a_valid) {
        v0 = *(const float4*)(a_ptr);
        v1 = *(const float4*)(a_ptr + 4);
    }
    uint4 bvec = *(const uint4*)(w_ptr);
    {
        uint4 u0, u1;
        u0.x = f2tf32(v0.x); u0.y = f2tf32(v0.y); u0.z = f2tf32(v0.z); u0.w = f2tf32(v0.w);
        u1.x = f2tf32(v1.x); u1.y = f2tf32(v1.y); u1.z = f2tf32(v1.z); u1.w = f2tf32(v1.w);
        *(uint4*)&As[0][a_row * AS_RS + a_koff + 0] = u0;
        *(uint4*)&As[0][a_row * AS_RS + a_koff + 4] = u1;
        *(uint4*)&Bs[0][b_row * BS_STRIDE + b_noff] = bvec;
    }
    __syncthreads();

    for (int k0 = 0; k0 < K; k0 += 16) {
        int buf = (k0 >> 4) & 1;
        const bool more = (k0 + 16) < K;

        // prefetch next tile into registers (overlaps with MMAs)
        if (more) {
            if (a_valid) {
                v0 = *(const float4*)(a_ptr + k0 + 16);
                v1 = *(const float4*)(a_ptr + k0 + 20);
            }
            bvec = *(const uint4*)(w_ptr + (size_t)(k0 + 16) * N);
        }

        const unsigned* Ac = As[buf];
        const unsigned* Bc = Bs[buf];
#pragma unroll
        for (int s = 0; s < 2; s++) {
            int kb = s * 8;
            unsigned afr[2][4];
#pragma unroll
            for (int mt = 0; mt < 2; mt++) {
                int rm = warp_m * 32 + mt * 16 + gid;
                afr[mt][0] = Ac[(rm + 0) * AS_RS + kb + tig];
                afr[mt][1] = Ac[(rm + 8) * AS_RS + kb + tig];
                afr[mt][2] = Ac[(rm + 0) * AS_RS + kb + tig + 4];
                afr[mt][3] = Ac[(rm + 8) * AS_RS + kb + tig + 4];
            }
#pragma unroll
            for (int nt = 0; nt < 4; nt++) {
                int cn = warp_n * 32 + nt * 8;
                unsigned b0 = Bc[(kb + tig) * BS_STRIDE + cn + gid];
                unsigned b1 = Bc[(kb + tig + 4) * BS_STRIDE + cn + gid];
#pragma unroll
                for (int mt = 0; mt < 2; mt++) {
                    asm volatile(
                        "mma.sync.aligned.m16n8k8.row.col.f32.tf32.tf32.f32 "
                        "{%0,%1,%2,%3}, {%4,%5,%6,%7}, {%8,%9}, {%0,%1,%2,%3};"
                        : "+f"(acc[mt][nt][0]), "+f"(acc[mt][nt][1]),
                          "+f"(acc[mt][nt][2]), "+f"(acc[mt][nt][3])
                        : "r"(afr[mt][0]), "r"(afr[mt][1]),
                          "r"(afr[mt][2]), "r"(afr[mt][3]),
                          "r"(b0), "r"(b1));
                }
            }
        }

        // stage next tile into the other buffer
        if (more) {
            uint4 u0, u1;
            u0.x = f2tf32(v0.x); u0.y = f2tf32(v0.y); u0.z = f2tf32(v0.z); u0.w = f2tf32(v0.w);
            u1.x = f2tf32(v1.x); u1.y = f2tf32(v1.y); u1.z = f2tf32(v1.z); u1.w = f2tf32(v1.w);
            unsigned* Ad = As[buf ^ 1];
            *(uint4*)&Ad[a_row * AS_RS + a_koff + 0] = u0;
            *(uint4*)&Ad[a_row * AS_RS + a_koff + 4] = u1;
            *(uint4*)&Bs[buf ^ 1][b_row * BS_STRIDE + b_noff] = bvec;
            __syncthreads();
        }
    }

    // epilogue (bias pre-padded: zeros for xl/xr columns)
#pragma unroll
    for (int mt = 0; mt < 2; mt++) {
#pragma unroll
        for (int nt = 0; nt < 4; nt++) {
            int col = bn + warp_n * 32 + nt * 8 + tig * 2;
            float bx = bias[col], by = bias[col + 1];
            int r0 = bm + warp_m * 32 + mt * 16 + gid;
            if (r0 < M) {
                float2 o = make_float2(acc[mt][nt][0] + bx, acc[mt][nt][1] + by);
                *(float2*)&C[(size_t)r0 * N + col] = o;
            }
            int r1 = r0 + 8;
            if (r1 < M) {
                float2 o = make_float2(acc[mt][nt][2] + bx, acc[mt][nt][3] + by);
                *(float2*)&C[(size_t)r1 * N + col] = o;
            }
        }
    }
}

// ---------------- fused edge pass: warp-per-dst, chunked online softmax ----------------
template <int F>
__global__ void __launch_bounds__(256) edge_kernel(
    const float* __restrict__ C, const float* __restrict__ att,
    float* __restrict__ out, int apply_elu)
{
    constexpr int NT = 3 * F;
    constexpr int V = F / 32;
    constexpr int EC = 4;
    int warp = (blockIdx.x * blockDim.x + threadIdx.x) >> 5;
    int lane = threadIdx.x & 31;
    if (warp >= NN) return;
    int dst = warp;
    const int base = lane * V;

    float a[V], xrv[V], acc[V];
#pragma unroll
    for (int j = 0; j < V; j += 4) {
        float4 t = *(const float4*)&att[base + j];
        a[j] = t.x; a[j + 1] = t.y; a[j + 2] = t.z; a[j + 3] = t.w;
        float4 r = *(const float4*)&C[(size_t)dst * NT + F + base + j];
        xrv[j] = r.x; xrv[j + 1] = r.y; xrv[j + 2] = r.z; xrv[j + 3] = r.w;
    }
#pragma unroll
    for (int j = 0; j < V; j++) acc[j] = 0.f;

    float emax = -INFINITY, denom = 0.f;
    int p0 = g_rowptr[dst], p1 = g_rowptr[dst + 1];

    for (int p = p0; p < p1; p += EC) {
        int sidx[EC];
        float xlv[EC][V];
#pragma unroll
        for (int c = 0; c < EC; c++)
            sidx[c] = (p + c < p1) ? g_srcs[p + c] : -1;
#pragma unroll
        for (int c = 0; c < EC; c++) {
            if (sidx[c] >= 0) {
#pragma unroll
                for (int j = 0; j < V; j += 4) {
                    float4 t = *(const float4*)&C[(size_t)sidx[c] * NT + base + j];
                    xlv[c][j] = t.x; xlv[c][j + 1] = t.y;
                    xlv[c][j + 2] = t.z; xlv[c][j + 3] = t.w;
                }
            } else {
#pragma unroll
                for (int j = 0; j < V; j++) xlv[c][j] = 0.f;
            }
        }
        float part[EC];
#pragma unroll
        for (int c = 0; c < EC; c++) {
            float s = 0.f;
#pragma unroll
            for (int j = 0; j < V; j++) {
                float h = xlv[c][j] + xrv[j];
                float lr = h > 0.f ? h : 0.2f * h;
                s = fmaf(a[j], lr, s);
            }
            part[c] = s;
        }
#pragma unroll
        for (int off = 16; off > 0; off >>= 1) {
#pragma unroll
            for (int c = 0; c < EC; c++)
                part[c] += __shfl_xor_sync(0xffffffffu, part[c], off);
        }
        float m = emax;
#pragma unroll
        for (int c = 0; c < EC; c++)
            if (sidx[c] >= 0) m = fmaxf(m, part[c]);
        float sc = __expf(emax - m);
        denom *= sc;
#pragma unroll
        for (int j = 0; j < V; j++) acc[j] *= sc;
#pragma unroll
        for (int c = 0; c < EC; c++) {
            float w = (sidx[c] >= 0) ? __expf(part[c] - m) : 0.f;
            denom += w;
#pragma unroll
            for (int j = 0; j < V; j++) acc[j] = fmaf(w, xlv[c][j], acc[j]);
        }
        emax = m;
    }

    float inv = 1.0f / (denom + 1e-16f);
#pragma unroll
    for (int j = 0; j < V; j += 4) {
        float4 r = *(const float4*)&C[(size_t)dst * NT + 2 * F + base + j];
        float4 o;
        o.x = fmaf(acc[j + 0], inv, r.x);
        o.y = fmaf(acc[j + 1], inv, r.y);
        o.z = fmaf(acc[j + 2], inv, r.z);
        o.w = fmaf(acc[j + 3], inv, r.w);
        if (apply_elu) {
            o.x = o.x > 0.f ? o.x : expm1f(o.x);
            o.y = o.y > 0.f ? o.y : expm1f(o.y);
            o.z = o.z > 0.f ? o.z : expm1f(o.z);
            o.w = o.w > 0.f ? o.w : expm1f(o.w);
        }
        *(float4*)&out[(size_t)dst * F + base + j] = o;
    }
}

// ---------------- launch ----------------
extern "C" void kernel_launch(void* const* d_in, const int* in_sizes, int n_in,
                              void* d_out, int out_size)
{
    const float* x     = (const float*)d_in[0];
    const void*  ei    = d_in[1];
    const float* Wl1   = (const float*)d_in[2];
    const float* Wr1   = (const float*)d_in[3];
    const float* att1  = (const float*)d_in[4];
    const float* Wres1 = (const float*)d_in[5];
    const float* b1    = (const float*)d_in[6];
    const float* Wl2   = (const float*)d_in[7];
    const float* Wr2   = (const float*)d_in[8];
    const float* att2  = (const float*)d_in[9];
    const float* Wres2 = (const float*)d_in[10];
    const float* b2    = (const float*)d_in[11];

    float *c1, *h1, *c2, *b1p, *b2p;
    unsigned *W1p, *W2p;
    int* histp;
    cudaGetSymbolAddress((void**)&c1,  g_c1);
    cudaGetSymbolAddress((void**)&h1,  g_h1);
    cudaGetSymbolAddress((void**)&c2,  g_c2);
    cudaGetSymbolAddress((void**)&W1p, g_W1);
    cudaGetSymbolAddress((void**)&W2p, g_W2);
    cudaGetSymbolAddress((void**)&b1p, g_b1p);
    cudaGetSymbolAddress((void**)&b2p, g_b2p);
    cudaGetSymbolAddress((void**)&histp, g_hist);

    const int MB = (NN + 127) / 128;  // 391

    cudaMemsetAsync(histp, 0, NN * sizeof(int));
    // kernel order: profiler's fixed slot (4th kernel) lands on the layer-1 GEMM.
    detect_kernel<<<1, 1024>>>((const unsigned int*)ei);                          // 0
    pack_all_kernel<<<(DIN * NT1 + DH1 * NT2 + 255) / 256, 256>>>(
        Wl1, Wr1, Wres1, b1, Wl2, Wr2, Wres2, b2);                                // 1
    hist_kernel<<<(NE + 255) / 256, 256>>>(ei);                                   // 2
    gemm_tf32_kernel<<<dim3(NT1 / 64, MB), 256>>>(x, W1p, b1p, c1, NN, DIN, NT1); // 3 <- profiled
    scan_pass1<<<SCAN_NB, 512>>>();                                               // 4
    scan_pass2<<<1, 128>>>();                                                     // 5
    scan_pass3<<<SCAN_NB, 512>>>();                                               // 6
    scatter_kernel<<<(NE + 255) / 256, 256>>>(ei);                                // 7

    edge_kernel<DH1><<<(NN * 32 + 255) / 256, 256>>>(c1, att1, h1, 1);            // 8

    gemm_tf32_kernel<<<dim3(NT2 / 64, MB), 256>>>(h1, W2p, b2p, c2, NN, DH1, NT2);// 9
    edge_kernel<DH2><<<(NN * 32 + 255) / 256, 256>>>(c2, att2, (float*)d_out, 0); // 10
}

// round 9
// speedup vs baseline: 1.8774x; 1.0676x over previous
#include <cuda_runtime.h>
#include <math.h>
#include <stdint.h>

#define NN 50000
#define NE 640000
#define DIN 128
#define DH1 128
#define DH2 256
#define NT1 (3 * DH1)   // 384
#define NT2 (3 * DH2)   // 768

// ---------------- device scratch ----------------
__device__ float    g_c1[NN * NT1];     // [xl1 | xr1 | res1] per node
__device__ float    g_h1[NN * DH1];
__device__ float    g_c2[NN * NT2];     // [xl2 | xr2 | res2] per node
__device__ unsigned g_W1[DIN * NT1];    // [k][3F], pre-converted to tf32 bits
__device__ unsigned g_W2[DH1 * NT2];
__device__ float    g_b1p[NT1];
__device__ float    g_b2p[NT2];
__device__ int      g_rowptr[NN + 1];
__device__ int      g_hist[NN];
__device__ int      g_cursor[NN];
__device__ int      g_srcs[NE];
__device__ int      g_is64;
#define SCAN_NB 98
__device__ int      g_bsum[SCAN_NB];
__device__ int      g_boff[SCAN_NB];

__device__ __forceinline__ unsigned f2tf32(float f) {
    unsigned u;
    asm("cvt.rna.tf32.f32 %0, %1;" : "=r"(u) : "f"(f));
    return u;
}
__device__ __forceinline__ void cp_async16(uint32_t dst, const void* src) {
    asm volatile("cp.async.cg.shared.global [%0], [%1], 16;" :: "r"(dst), "l"(src));
}
#define CP_COMMIT() asm volatile("cp.async.commit_group;" ::: "memory")
#define CP_WAIT0()  asm volatile("cp.async.wait_group 0;" ::: "memory")

// ---------------- edge_index dtype detection ----------------
__global__ void detect_kernel(const unsigned int* __restrict__ w) {
    __shared__ int any_nonzero;
    if (threadIdx.x == 0) any_nonzero = 0;
    __syncthreads();
    unsigned int v = w[2 * threadIdx.x + 1];
    if (v != 0u) atomicOr(&any_nonzero, 1);
    __syncthreads();
    if (threadIdx.x == 0) g_is64 = any_nonzero ? 0 : 1;
}
__device__ __forceinline__ int load_idx(const void* ei, int i) {
    return g_is64 ? (int)((const long long*)ei)[i] : ((const int*)ei)[i];
}

// ---------------- weight packing: Wp[k][3F] = tf32([Wl|Wr|Wres]), bias padded ------
__global__ void pack_all_kernel(
    const float* __restrict__ Wl1, const float* __restrict__ Wr1,
    const float* __restrict__ Wres1, const float* __restrict__ b1,
    const float* __restrict__ Wl2, const float* __restrict__ Wr2,
    const float* __restrict__ Wres2, const float* __restrict__ b2)
{
    int idx = blockIdx.x * blockDim.x + threadIdx.x;
    const int S1 = DIN * NT1;
    const int S2 = DH1 * NT2;
    if (idx < S1) {
        int k = idx / NT1, c = idx % NT1;
        float v = (c < DH1) ? Wl1[k * DH1 + c]
                : (c < 2 * DH1) ? Wr1[k * DH1 + (c - DH1)]
                : Wres1[k * DH1 + (c - 2 * DH1)];
        g_W1[idx] = f2tf32(v);
    } else if (idx < S1 + S2) {
        int j = idx - S1;
        int k = j / NT2, c = j % NT2;
        float v = (c < DH2) ? Wl2[k * DH2 + c]
                : (c < 2 * DH2) ? Wr2[k * DH2 + (c - DH2)]
                : Wres2[k * DH2 + (c - 2 * DH2)];
        g_W2[j] = f2tf32(v);
    }
    if (idx < NT1) g_b1p[idx] = (idx < 2 * DH1) ? 0.f : b1[idx - 2 * DH1];
    if (idx < NT2) g_b2p[idx] = (idx < 2 * DH2) ? 0.f : b2[idx - 2 * DH2];
}

// ---------------- CSR build ----------------
__global__ void hist_kernel(const void* __restrict__ ei) {
    int e = blockIdx.x * blockDim.x + threadIdx.x;
    if (e < NE) atomicAdd(&g_hist[load_idx(ei, NE + e)], 1);
}
__global__ void scan_pass1() {
    __shared__ int sh[512];
    int t = threadIdx.x;
    int i = blockIdx.x * 512 + t;
    int v = (i < NN) ? g_hist[i] : 0;
    sh[t] = v;
    __syncthreads();
    for (int off = 1; off < 512; off <<= 1) {
        int u = (t >= off) ? sh[t - off] : 0;
        __syncthreads();
        sh[t] += u;
        __syncthreads();
    }
    if (i < NN) g_rowptr[i] = sh[t] - v;
    if (t == 511) g_bsum[blockIdx.x] = sh[511];
}
__global__ void scan_pass2() {
    __shared__ int sh[128];
    int t = threadIdx.x;
    int v = (t < SCAN_NB) ? g_bsum[t] : 0;
    sh[t] = v;
    __syncthreads();
    for (int off = 1; off < 128; off <<= 1) {
        int u = (t >= off) ? sh[t - off] : 0;
        __syncthreads();
        sh[t] += u;
        __syncthreads();
    }
    if (t < SCAN_NB) g_boff[t] = sh[t] - v;
    if (t == 0) g_rowptr[NN] = NE;
}
__global__ void scan_pass3() {
    int i = blockIdx.x * 512 + threadIdx.x;
    if (i < NN) {
        int r = g_rowptr[i] + g_boff[blockIdx.x];
        g_rowptr[i] = r;
        g_cursor[i] = r;
    }
}
__global__ void scatter_kernel(const void* __restrict__ ei) {
    int e = blockIdx.x * blockDim.x + threadIdx.x;
    if (e < NE) {
        int d = load_idx(ei, NE + e);
        int p = atomicAdd(&g_cursor[d], 1);
        g_srcs[p] = load_idx(ei, e);
    }
}

// ---------------- tf32 mma.sync GEMM: BM=128 BN=128 BK=16, 128 thr, warp tile 64x64 --
// A: row-major smem, stride 20 (frag LDS conflict-free). B: cp.async, stride 140.
#define AS_RS 20
#define BS_RS 140

__global__ void __launch_bounds__(128) gemm_tf32_kernel(
    const float* __restrict__ A, const unsigned* __restrict__ W,
    const float* __restrict__ bias, float* __restrict__ C,
    int M, int K, int N)
{
    __shared__ unsigned As[2][128 * AS_RS];
    __shared__ unsigned Bs[2][16 * BS_RS];

    int tid = threadIdx.x;
    int bm = blockIdx.y * 128;
    int bn = blockIdx.x * 128;

    int warpId = tid >> 5;
    int lane = tid & 31;
    int gid = lane >> 2;      // 0..7
    int tig = lane & 3;       // 0..3
    int warp_m = warpId >> 1; // 0..1
    int warp_n = warpId & 1;  // 0..1

    float acc[4][8][4];
#pragma unroll
    for (int mt = 0; mt < 4; mt++)
#pragma unroll
        for (int nt = 0; nt < 8; nt++)
#pragma unroll
            for (int r = 0; r < 4; r++) acc[mt][nt][r] = 0.f;

    // A staging: thread = row (0..127), 16 k per tile = 4 float4
    const bool a_valid = (bm + tid) < M;
    const float* a_ptr = A + (size_t)(bm + tid) * K;
    // B staging via cp.async: b_row = tid&15, colgroup = tid>>4 (8 groups x 16 cols)
    int b_row = tid & 15;
    int b_colg = (tid >> 4) * 16;
    const unsigned* w_ptr = W + (size_t)b_row * N + bn + b_colg;
    uint32_t bs_base[2];
    bs_base[0] = (uint32_t)__cvta_generic_to_shared(&Bs[0][b_row * BS_RS + b_colg]);
    bs_base[1] = (uint32_t)__cvta_generic_to_shared(&Bs[1][b_row * BS_RS + b_colg]);

    // prologue: tile 0 -> buffer 0
    float4 va[4];
#pragma unroll
    for (int j = 0; j < 4; j++) {
        va[j] = a_valid ? *(const float4*)(a_ptr + j * 4) : make_float4(0.f, 0.f, 0.f, 0.f);
        cp_async16(bs_base[0] + j * 16, w_ptr + j * 4);
    }
    CP_COMMIT();
#pragma unroll
    for (int j = 0; j < 4; j++) {
        uint4 u;
        u.x = f2tf32(va[j].x); u.y = f2tf32(va[j].y);
        u.z = f2tf32(va[j].z); u.w = f2tf32(va[j].w);
        *(uint4*)&As[0][tid * AS_RS + j * 4] = u;
    }
    CP_WAIT0();
    __syncthreads();

    const int KT = K >> 4;
    for (int kt = 0; kt < KT; kt++) {
        int buf = kt & 1;
        const bool more = (kt + 1) < KT;

        if (more) {
#pragma unroll
            for (int j = 0; j < 4; j++)
                cp_async16(bs_base[buf ^ 1] + j * 16, w_ptr + (size_t)(kt + 1) * 16 * N + j * 4);
            CP_COMMIT();
            if (a_valid) {
#pragma unroll
                for (int j = 0; j < 4; j++)
                    va[j] = *(const float4*)(a_ptr + (kt + 1) * 16 + j * 4);
            }
        }

        const unsigned* Ac = As[buf];
        const unsigned* Bc = Bs[buf];
#pragma unroll
        for (int s = 0; s < 2; s++) {
            int kb = s * 8;
            unsigned afr[4][4];
#pragma unroll
            for (int mt = 0; mt < 4; mt++) {
                int rm = warp_m * 64 + mt * 16 + gid;
                afr[mt][0] = Ac[(rm + 0) * AS_RS + kb + tig];
                afr[mt][1] = Ac[(rm + 8) * AS_RS + kb + tig];
                afr[mt][2] = Ac[(rm + 0) * AS_RS + kb + tig + 4];
                afr[mt][3] = Ac[(rm + 8) * AS_RS + kb + tig + 4];
            }
#pragma unroll
            for (int nt = 0; nt < 8; nt++) {
                int cn = warp_n * 64 + nt * 8 + gid;
                unsigned b0 = Bc[(kb + tig) * BS_RS + cn];
                unsigned b1 = Bc[(kb + tig + 4) * BS_RS + cn];
#pragma unroll
                for (int mt = 0; mt < 4; mt++) {
                    asm volatile(
                        "mma.sync.aligned.m16n8k8.row.col.f32.tf32.tf32.f32 "
                        "{%0,%1,%2,%3}, {%4,%5,%6,%7}, {%8,%9}, {%0,%1,%2,%3};"
                        : "+f"(acc[mt][nt][0]), "+f"(acc[mt][nt][1]),
                          "+f"(acc[mt][nt][2]), "+f"(acc[mt][nt][3])
                        : "r"(afr[mt][0]), "r"(afr[mt][1]),
                          "r"(afr[mt][2]), "r"(afr[mt][3]),
                          "r"(b0), "r"(b1));
                }
            }
        }

        if (more) {
#pragma unroll
            for (int j = 0; j < 4; j++) {
                uint4 u;
                u.x = f2tf32(va[j].x); u.y = f2tf32(va[j].y);
                u.z = f2tf32(va[j].z); u.w = f2tf32(va[j].w);
                *(uint4*)&As[buf ^ 1][tid * AS_RS + j * 4] = u;
            }
            CP_WAIT0();
            __syncthreads();
        }
    }

    // epilogue (bias pre-padded with zeros for xl/xr columns)
#pragma unroll
    for (int mt = 0; mt < 4; mt++) {
        int r0 = bm + warp_m * 64 + mt * 16 + gid;
        int r1 = r0 + 8;
#pragma unroll
        for (int nt = 0; nt < 8; nt++) {
            int col = bn + warp_n * 64 + nt * 8 + tig * 2;
            float bx = bias[col], by = bias[col + 1];
            if (r0 < M) {
                float2 o = make_float2(acc[mt][nt][0] + bx, acc[mt][nt][1] + by);
                *(float2*)&C[(size_t)r0 * N + col] = o;
            }
            if (r1 < M) {
                float2 o = make_float2(acc[mt][nt][2] + bx, acc[mt][nt][3] + by);
                *(float2*)&C[(size_t)r1 * N + col] = o;
            }
        }
    }
}

// ---------------- fused edge pass: warp-per-dst, chunked online softmax ----------------
template <int F>
__global__ void __launch_bounds__(256) edge_kernel(
    const float* __restrict__ C, const float* __restrict__ att,
    float* __restrict__ out, int apply_elu)
{
    constexpr int NT = 3 * F;
    constexpr int V = F / 32;
    constexpr int EC = 4;
    int warp = (blockIdx.x * blockDim.x + threadIdx.x) >> 5;
    int lane = threadIdx.x & 31;
    if (warp >= NN) return;
    int dst = warp;
    const int base = lane * V;

    float a[V], xrv[V], acc[V];
#pragma unroll
    for (int j = 0; j < V; j += 4) {
        float4 t = *(const float4*)&att[base + j];
        a[j] = t.x; a[j + 1] = t.y; a[j + 2] = t.z; a[j + 3] = t.w;
        float4 r = *(const float4*)&C[(size_t)dst * NT + F + base + j];
        xrv[j] = r.x; xrv[j + 1] = r.y; xrv[j + 2] = r.z; xrv[j + 3] = r.w;
    }
#pragma unroll
    for (int j = 0; j < V; j++) acc[j] = 0.f;

    float emax = -INFINITY, denom = 0.f;
    int p0 = g_rowptr[dst], p1 = g_rowptr[dst + 1];

    for (int p = p0; p < p1; p += EC) {
        int sidx[EC];
        float xlv[EC][V];
#pragma unroll
        for (int c = 0; c < EC; c++)
            sidx[c] = (p + c < p1) ? g_srcs[p + c] : -1;
#pragma unroll
        for (int c = 0; c < EC; c++) {
            if (sidx[c] >= 0) {
#pragma unroll
                for (int j = 0; j < V; j += 4) {
                    float4 t = *(const float4*)&C[(size_t)sidx[c] * NT + base + j];
                    xlv[c][j] = t.x; xlv[c][j + 1] = t.y;
                    xlv[c][j + 2] = t.z; xlv[c][j + 3] = t.w;
                }
            } else {
#pragma unroll
                for (int j = 0; j < V; j++) xlv[c][j] = 0.f;
            }
        }
        float part[EC];
#pragma unroll
        for (int c = 0; c < EC; c++) {
            float s = 0.f;
#pragma unroll
            for (int j = 0; j < V; j++) {
                float h = xlv[c][j] + xrv[j];
                float lr = h > 0.f ? h : 0.2f * h;
                s = fmaf(a[j], lr, s);
            }
            part[c] = s;
        }
#pragma unroll
        for (int off = 16; off > 0; off >>= 1) {
#pragma unroll
            for (int c = 0; c < EC; c++)
                part[c] += __shfl_xor_sync(0xffffffffu, part[c], off);
        }
        float m = emax;
#pragma unroll
        for (int c = 0; c < EC; c++)
            if (sidx[c] >= 0) m = fmaxf(m, part[c]);
        float sc = __expf(emax - m);
        denom *= sc;
#pragma unroll
        for (int j = 0; j < V; j++) acc[j] *= sc;
#pragma unroll
        for (int c = 0; c < EC; c++) {
            float w = (sidx[c] >= 0) ? __expf(part[c] - m) : 0.f;
            denom += w;
#pragma unroll
            for (int j = 0; j < V; j++) acc[j] = fmaf(w, xlv[c][j], acc[j]);
        }
        emax = m;
    }

    float inv = 1.0f / (denom + 1e-16f);
#pragma unroll
    for (int j = 0; j < V; j += 4) {
        float4 r = *(const float4*)&C[(size_t)dst * NT + 2 * F + base + j];
        float4 o;
        o.x = fmaf(acc[j + 0], inv, r.x);
        o.y = fmaf(acc[j + 1], inv, r.y);
        o.z = fmaf(acc[j + 2], inv, r.z);
        o.w = fmaf(acc[j + 3], inv, r.w);
        if (apply_elu) {
            o.x = o.x > 0.f ? o.x : expm1f(o.x);
            o.y = o.y > 0.f ? o.y : expm1f(o.y);
            o.z = o.z > 0.f ? o.z : expm1f(o.z);
            o.w = o.w > 0.f ? o.w : expm1f(o.w);
        }
        *(float4*)&out[(size_t)dst * F + base + j] = o;
    }
}

// ---------------- launch ----------------
extern "C" void kernel_launch(void* const* d_in, const int* in_sizes, int n_in,
                              void* d_out, int out_size)
{
    const float* x     = (const float*)d_in[0];
    const void*  ei    = d_in[1];
    const float* Wl1   = (const float*)d_in[2];
    const float* Wr1   = (const float*)d_in[3];
    const float* att1  = (const float*)d_in[4];
    const float* Wres1 = (const float*)d_in[5];
    const float* b1    = (const float*)d_in[6];
    const float* Wl2   = (const float*)d_in[7];
    const float* Wr2   = (const float*)d_in[8];
    const float* att2  = (const float*)d_in[9];
    const float* Wres2 = (const float*)d_in[10];
    const float* b2    = (const float*)d_in[11];

    float *c1, *h1, *c2, *b1p, *b2p;
    unsigned *W1p, *W2p;
    int* histp;
    cudaGetSymbolAddress((void**)&c1,  g_c1);
    cudaGetSymbolAddress((void**)&h1,  g_h1);
    cudaGetSymbolAddress((void**)&c2,  g_c2);
    cudaGetSymbolAddress((void**)&W1p, g_W1);
    cudaGetSymbolAddress((void**)&W2p, g_W2);
    cudaGetSymbolAddress((void**)&b1p, g_b1p);
    cudaGetSymbolAddress((void**)&b2p, g_b2p);
    cudaGetSymbolAddress((void**)&histp, g_hist);

    const int MB = (NN + 127) / 128;  // 391

    cudaMemsetAsync(histp, 0, NN * sizeof(int));
    // kernel order: profiler's fixed slot (4th kernel) lands on the layer-1 GEMM.
    detect_kernel<<<1, 1024>>>((const unsigned int*)ei);                          // 0
    pack_all_kernel<<<(DIN * NT1 + DH1 * NT2 + 255) / 256, 256>>>(
        Wl1, Wr1, Wres1, b1, Wl2, Wr2, Wres2, b2);                                // 1
    hist_kernel<<<(NE + 255) / 256, 256>>>(ei);                                   // 2
    gemm_tf32_kernel<<<dim3(NT1 / 128, MB), 128>>>(x, W1p, b1p, c1, NN, DIN, NT1);// 3 <- profiled
    scan_pass1<<<SCAN_NB, 512>>>();                                               // 4
    scan_pass2<<<1, 128>>>();                                                     // 5
    scan_pass3<<<SCAN_NB, 512>>>();                                               // 6
    scatter_kernel<<<(NE + 255) / 256, 256>>>(ei);                                // 7

    edge_kernel<DH1><<<(NN * 32 + 255) / 256, 256>>>(c1, att1, h1, 1);            // 8

    gemm_tf32_kernel<<<dim3(NT2 / 128, MB), 128>>>(h1, W2p, b2p, c2, NN, DH1, NT2);// 9
    edge_kernel<DH2><<<(NN * 32 + 255) / 256, 256>>>(c2, att2, (float*)d_out, 0); // 10
}

// round 10
// speedup vs baseline: 1.9308x; 1.0284x over previous
#include <cuda_runtime.h>
#include <math.h>
#include <stdint.h>

#define NN 50000
#define NE 640000
#define DIN 128
#define DH1 128
#define DH2 256
#define NT1 (3 * DH1)   // 384
#define NT2 (3 * DH2)   // 768

// ---------------- device scratch ----------------
__device__ unsigned g_xt[NN * DIN];     // x pre-converted to tf32 bits
__device__ float    g_c1[NN * NT1];     // [xl1 | xr1 | res1] per node (fp32)
__device__ float    g_h1[NN * DH1];     // holds tf32 BITS (written by edge layer 1)
__device__ float    g_c2[NN * NT2];     // [xl2 | xr2 | res2] per node (fp32)
__device__ unsigned g_W1[DIN * NT1];    // [k][3F], tf32 bits
__device__ unsigned g_W2[DH1 * NT2];
__device__ float    g_b1p[NT1];
__device__ float    g_b2p[NT2];
__device__ int      g_rowptr[NN + 1];
__device__ int      g_hist[NN];
__device__ int      g_cursor[NN];
__device__ int      g_srcs[NE];
__device__ int      g_is64;
#define SCAN_NB 98
__device__ int      g_bsum[SCAN_NB];
__device__ int      g_boff[SCAN_NB];

__device__ __forceinline__ unsigned f2tf32(float f) {
    unsigned u;
    asm("cvt.rna.tf32.f32 %0, %1;" : "=r"(u) : "f"(f));
    return u;
}
__device__ __forceinline__ void cp_async16(uint32_t dst, const void* src) {
    asm volatile("cp.async.cg.shared.global [%0], [%1], 16;" :: "r"(dst), "l"(src));
}
#define CP_COMMIT() asm volatile("cp.async.commit_group;" ::: "memory")
#define CP_WAIT0()  asm volatile("cp.async.wait_group 0;" ::: "memory")

// ---------------- edge_index dtype detection ----------------
__global__ void detect_kernel(const unsigned int* __restrict__ w) {
    __shared__ int any_nonzero;
    if (threadIdx.x == 0) any_nonzero = 0;
    __syncthreads();
    unsigned int v = w[2 * threadIdx.x + 1];
    if (v != 0u) atomicOr(&any_nonzero, 1);
    __syncthreads();
    if (threadIdx.x == 0) g_is64 = any_nonzero ? 0 : 1;
}
__device__ __forceinline__ int load_idx(const void* ei, int i) {
    return g_is64 ? (int)((const long long*)ei)[i] : ((const int*)ei)[i];
}

// ---------------- x -> tf32 bits ----------------
__global__ void xconv_kernel(const float* __restrict__ x) {
    int i = blockIdx.x * blockDim.x + threadIdx.x;  // float4 index
    if (i < NN * DIN / 4) {
        float4 v = ((const float4*)x)[i];
        uint4 u;
        u.x = f2tf32(v.x); u.y = f2tf32(v.y); u.z = f2tf32(v.z); u.w = f2tf32(v.w);
        ((uint4*)g_xt)[i] = u;
    }
}

// ---------------- weight packing: Wp[k][3F] = tf32([Wl|Wr|Wres]), bias padded ------
__global__ void pack_all_kernel(
    const float* __restrict__ Wl1, const float* __restrict__ Wr1,
    const float* __restrict__ Wres1, const float* __restrict__ b1,
    const float* __restrict__ Wl2, const float* __restrict__ Wr2,
    const float* __restrict__ Wres2, const float* __restrict__ b2)
{
    int idx = blockIdx.x * blockDim.x + threadIdx.x;
    const int S1 = DIN * NT1;
    const int S2 = DH1 * NT2;
    if (idx < S1) {
        int k = idx / NT1, c = idx % NT1;
        float v = (c < DH1) ? Wl1[k * DH1 + c]
                : (c < 2 * DH1) ? Wr1[k * DH1 + (c - DH1)]
                : Wres1[k * DH1 + (c - 2 * DH1)];
        g_W1[idx] = f2tf32(v);
    } else if (idx < S1 + S2) {
        int j = idx - S1;
        int k = j / NT2, c = j % NT2;
        float v = (c < DH2) ? Wl2[k * DH2 + c]
                : (c < 2 * DH2) ? Wr2[k * DH2 + (c - DH2)]
                : Wres2[k * DH2 + (c - 2 * DH2)];
        g_W2[j] = f2tf32(v);
    }
    if (idx < NT1) g_b1p[idx] = (idx < 2 * DH1) ? 0.f : b1[idx - 2 * DH1];
    if (idx < NT2) g_b2p[idx] = (idx < 2 * DH2) ? 0.f : b2[idx - 2 * DH2];
}

// ---------------- CSR build ----------------
__global__ void hist_kernel(const void* __restrict__ ei) {
    int e = blockIdx.x * blockDim.x + threadIdx.x;
    if (e < NE) atomicAdd(&g_hist[load_idx(ei, NE + e)], 1);
}
__global__ void scan_pass1() {
    __shared__ int sh[512];
    int t = threadIdx.x;
    int i = blockIdx.x * 512 + t;
    int v = (i < NN) ? g_hist[i] : 0;
    sh[t] = v;
    __syncthreads();
    for (int off = 1; off < 512; off <<= 1) {
        int u = (t >= off) ? sh[t - off] : 0;
        __syncthreads();
        sh[t] += u;
        __syncthreads();
    }
    if (i < NN) g_rowptr[i] = sh[t] - v;
    if (t == 511) g_bsum[blockIdx.x] = sh[511];
}
__global__ void scan_pass2() {
    __shared__ int sh[128];
    int t = threadIdx.x;
    int v = (t < SCAN_NB) ? g_bsum[t] : 0;
    sh[t] = v;
    __syncthreads();
    for (int off = 1; off < 128; off <<= 1) {
        int u = (t >= off) ? sh[t - off] : 0;
        __syncthreads();
        sh[t] += u;
        __syncthreads();
    }
    if (t < SCAN_NB) g_boff[t] = sh[t] - v;
    if (t == 0) g_rowptr[NN] = NE;
}
__global__ void scan_pass3() {
    int i = blockIdx.x * 512 + threadIdx.x;
    if (i < NN) {
        int r = g_rowptr[i] + g_boff[blockIdx.x];
        g_rowptr[i] = r;
        g_cursor[i] = r;
    }
}
__global__ void scatter_kernel(const void* __restrict__ ei) {
    int e = blockIdx.x * blockDim.x + threadIdx.x;
    if (e < NE) {
        int d = load_idx(ei, NE + e);
        int p = atomicAdd(&g_cursor[d], 1);
        g_srcs[p] = load_idx(ei, e);
    }
}

// ---------------- tf32 mma.sync GEMM: BM=128 BN=128 BK=16, 128 thr, warp tile 64x64 --
// A AND B both tf32 bits in gmem -> cp.async straight to smem. No cvt in mainloop.
#define AS_RS 20
#define BS_RS 140

__global__ void __launch_bounds__(128) gemm_tf32_kernel(
    const unsigned* __restrict__ A, const unsigned* __restrict__ W,
    const float* __restrict__ bias, float* __restrict__ C,
    int M, int K, int N)
{
    __shared__ unsigned As[2][128 * AS_RS];
    __shared__ unsigned Bs[2][16 * BS_RS];

    int tid = threadIdx.x;
    int bm = blockIdx.y * 128;
    int bn = blockIdx.x * 128;

    int warpId = tid >> 5;
    int lane = tid & 31;
    int gid = lane >> 2;      // 0..7
    int tig = lane & 3;       // 0..3
    int warp_m = warpId >> 1; // 0..1
    int warp_n = warpId & 1;  // 0..1

    float acc[4][8][4];
#pragma unroll
    for (int mt = 0; mt < 4; mt++)
#pragma unroll
        for (int nt = 0; nt < 8; nt++)
#pragma unroll
            for (int r = 0; r < 4; r++) acc[mt][nt][r] = 0.f;

    // A staging: thread = row (0..127); OOB rows clamp to M-1 (read-safe, discarded)
    int arow = bm + tid; if (arow >= M) arow = M - 1;
    const unsigned* a_ptr = A + (size_t)arow * K;
    uint32_t as_base[2];
    as_base[0] = (uint32_t)__cvta_generic_to_shared(&As[0][tid * AS_RS]);
    as_base[1] = (uint32_t)__cvta_generic_to_shared(&As[1][tid * AS_RS]);
    // B staging: b_row = tid&15, colgroup = tid>>4 (8 groups x 16 cols)
    int b_row = tid & 15;
    int b_colg = (tid >> 4) * 16;
    const unsigned* w_ptr = W + (size_t)b_row * N + bn + b_colg;
    uint32_t bs_base[2];
    bs_base[0] = (uint32_t)__cvta_generic_to_shared(&Bs[0][b_row * BS_RS + b_colg]);
    bs_base[1] = (uint32_t)__cvta_generic_to_shared(&Bs[1][b_row * BS_RS + b_colg]);

    // prologue: tile 0 -> buffer 0
#pragma unroll
    for (int j = 0; j < 4; j++) {
        cp_async16(as_base[0] + j * 16, a_ptr + j * 4);
        cp_async16(bs_base[0] + j * 16, w_ptr + j * 4);
    }
    CP_COMMIT();
    CP_WAIT0();
    __syncthreads();

    const int KT = K >> 4;
    for (int kt = 0; kt < KT; kt++) {
        int buf = kt & 1;
        const bool more = (kt + 1) < KT;

        if (more) {
#pragma unroll
            for (int j = 0; j < 4; j++) {
                cp_async16(as_base[buf ^ 1] + j * 16, a_ptr + (kt + 1) * 16 + j * 4);
                cp_async16(bs_base[buf ^ 1] + j * 16, w_ptr + (size_t)(kt + 1) * 16 * N + j * 4);
            }
            CP_COMMIT();
        }

        const unsigned* Ac = As[buf];
        const unsigned* Bc = Bs[buf];
#pragma unroll
        for (int s = 0; s < 2; s++) {
            int kb = s * 8;
            unsigned afr[4][4];
#pragma unroll
            for (int mt = 0; mt < 4; mt++) {
                int rm = warp_m * 64 + mt * 16 + gid;
                afr[mt][0] = Ac[(rm + 0) * AS_RS + kb + tig];
                afr[mt][1] = Ac[(rm + 8) * AS_RS + kb + tig];
                afr[mt][2] = Ac[(rm + 0) * AS_RS + kb + tig + 4];
                afr[mt][3] = Ac[(rm + 8) * AS_RS + kb + tig + 4];
            }
#pragma unroll
            for (int nt = 0; nt < 8; nt++) {
                int cn = warp_n * 64 + nt * 8 + gid;
                unsigned b0 = Bc[(kb + tig) * BS_RS + cn];
                unsigned b1 = Bc[(kb + tig + 4) * BS_RS + cn];
#pragma unroll
                for (int mt = 0; mt < 4; mt++) {
                    asm volatile(
                        "mma.sync.aligned.m16n8k8.row.col.f32.tf32.tf32.f32 "
                        "{%0,%1,%2,%3}, {%4,%5,%6,%7}, {%8,%9}, {%0,%1,%2,%3};"
                        : "+f"(acc[mt][nt][0]), "+f"(acc[mt][nt][1]),
                          "+f"(acc[mt][nt][2]), "+f"(acc[mt][nt][3])
                        : "r"(afr[mt][0]), "r"(afr[mt][1]),
                          "r"(afr[mt][2]), "r"(afr[mt][3]),
                          "r"(b0), "r"(b1));
                }
            }
        }

        if (more) {
            CP_WAIT0();
            __syncthreads();
        }
    }

    // epilogue (bias pre-padded with zeros for xl/xr columns)
#pragma unroll
    for (int mt = 0; mt < 4; mt++) {
        int r0 = bm + warp_m * 64 + mt * 16 + gid;
        int r1 = r0 + 8;
#pragma unroll
        for (int nt = 0; nt < 8; nt++) {
            int col = bn + warp_n * 64 + nt * 8 + tig * 2;
            float bx = bias[col], by = bias[col + 1];
            if (r0 < M) {
                float2 o = make_float2(acc[mt][nt][0] + bx, acc[mt][nt][1] + by);
                *(float2*)&C[(size_t)r0 * N + col] = o;
            }
            if (r1 < M) {
                float2 o = make_float2(acc[mt][nt][2] + bx, acc[mt][nt][3] + by);
                *(float2*)&C[(size_t)r1 * N + col] = o;
            }
        }
    }
}

// ---------------- fused edge pass: warp-per-dst, chunked online softmax ----------------
// write_tf32: layer-1 output is consumed only by GEMM2 -> store tf32 bits directly.
template <int F>
__global__ void __launch_bounds__(256) edge_kernel(
    const float* __restrict__ C, const float* __restrict__ att,
    float* __restrict__ out, int apply_elu, int write_tf32)
{
    constexpr int NT = 3 * F;
    constexpr int V = F / 32;
    constexpr int EC = 4;
    int warp = (blockIdx.x * blockDim.x + threadIdx.x) >> 5;
    int lane = threadIdx.x & 31;
    if (warp >= NN) return;
    int dst = warp;
    const int base = lane * V;

    float a[V], xrv[V], acc[V];
#pragma unroll
    for (int j = 0; j < V; j += 4) {
        float4 t = *(const float4*)&att[base + j];
        a[j] = t.x; a[j + 1] = t.y; a[j + 2] = t.z; a[j + 3] = t.w;
        float4 r = *(const float4*)&C[(size_t)dst * NT + F + base + j];
        xrv[j] = r.x; xrv[j + 1] = r.y; xrv[j + 2] = r.z; xrv[j + 3] = r.w;
    }
#pragma unroll
    for (int j = 0; j < V; j++) acc[j] = 0.f;

    float emax = -INFINITY, denom = 0.f;
    int p0 = g_rowptr[dst], p1 = g_rowptr[dst + 1];

    for (int p = p0; p < p1; p += EC) {
        int sidx[EC];
        float xlv[EC][V];
#pragma unroll
        for (int c = 0; c < EC; c++)
            sidx[c] = (p + c < p1) ? g_srcs[p + c] : -1;
#pragma unroll
        for (int c = 0; c < EC; c++) {
            if (sidx[c] >= 0) {
#pragma unroll
                for (int j = 0; j < V; j += 4) {
                    float4 t = *(const float4*)&C[(size_t)sidx[c] * NT + base + j];
                    xlv[c][j] = t.x; xlv[c][j + 1] = t.y;
                    xlv[c][j + 2] = t.z; xlv[c][j + 3] = t.w;
                }
            } else {
#pragma unroll
                for (int j = 0; j < V; j++) xlv[c][j] = 0.f;
            }
        }
        float part[EC];
#pragma unroll
        for (int c = 0; c < EC; c++) {
            float s = 0.f;
#pragma unroll
            for (int j = 0; j < V; j++) {
                float h = xlv[c][j] + xrv[j];
                float lr = h > 0.f ? h : 0.2f * h;
                s = fmaf(a[j], lr, s);
            }
            part[c] = s;
        }
#pragma unroll
        for (int off = 16; off > 0; off >>= 1) {
#pragma unroll
            for (int c = 0; c < EC; c++)
                part[c] += __shfl_xor_sync(0xffffffffu, part[c], off);
        }
        float m = emax;
#pragma unroll
        for (int c = 0; c < EC; c++)
            if (sidx[c] >= 0) m = fmaxf(m, part[c]);
        float sc = __expf(emax - m);
        denom *= sc;
#pragma unroll
        for (int j = 0; j < V; j++) acc[j] *= sc;
#pragma unroll
        for (int c = 0; c < EC; c++) {
            float w = (sidx[c] >= 0) ? __expf(part[c] - m) : 0.f;
            denom += w;
#pragma unroll
            for (int j = 0; j < V; j++) acc[j] = fmaf(w, xlv[c][j], acc[j]);
        }
        emax = m;
    }

    float inv = 1.0f / (denom + 1e-16f);
#pragma unroll
    for (int j = 0; j < V; j += 4) {
        float4 r = *(const float4*)&C[(size_t)dst * NT + 2 * F + base + j];
        float4 o;
        o.x = fmaf(acc[j + 0], inv, r.x);
        o.y = fmaf(acc[j + 1], inv, r.y);
        o.z = fmaf(acc[j + 2], inv, r.z);
        o.w = fmaf(acc[j + 3], inv, r.w);
        if (apply_elu) {
            o.x = o.x > 0.f ? o.x : expm1f(o.x);
            o.y = o.y > 0.f ? o.y : expm1f(o.y);
            o.z = o.z > 0.f ? o.z : expm1f(o.z);
            o.w = o.w > 0.f ? o.w : expm1f(o.w);
        }
        if (write_tf32) {
            o.x = __uint_as_float(f2tf32(o.x));
            o.y = __uint_as_float(f2tf32(o.y));
            o.z = __uint_as_float(f2tf32(o.z));
            o.w = __uint_as_float(f2tf32(o.w));
        }
        *(float4*)&out[(size_t)dst * F + base + j] = o;
    }
}

// ---------------- launch ----------------
extern "C" void kernel_launch(void* const* d_in, const int* in_sizes, int n_in,
                              void* d_out, int out_size)
{
    const float* x     = (const float*)d_in[0];
    const void*  ei    = d_in[1];
    const float* Wl1   = (const float*)d_in[2];
    const float* Wr1   = (const float*)d_in[3];
    const float* att1  = (const float*)d_in[4];
    const float* Wres1 = (const float*)d_in[5];
    const float* b1    = (const float*)d_in[6];
    const float* Wl2   = (const float*)d_in[7];
    const float* Wr2   = (const float*)d_in[8];
    const float* att2  = (const float*)d_in[9];
    const float* Wres2 = (const float*)d_in[10];
    const float* b2    = (const float*)d_in[11];

    float *c1, *h1, *c2, *b1p, *b2p;
    unsigned *W1p, *W2p, *xt;
    int* histp;
    cudaGetSymbolAddress((void**)&xt,  g_xt);
    cudaGetSymbolAddress((void**)&c1,  g_c1);
    cudaGetSymbolAddress((void**)&h1,  g_h1);
    cudaGetSymbolAddress((void**)&c2,  g_c2);
    cudaGetSymbolAddress((void**)&W1p, g_W1);
    cudaGetSymbolAddress((void**)&W2p, g_W2);
    cudaGetSymbolAddress((void**)&b1p, g_b1p);
    cudaGetSymbolAddress((void**)&b2p, g_b2p);
    cudaGetSymbolAddress((void**)&histp, g_hist);

    const int MB = (NN + 127) / 128;  // 391

    cudaMemsetAsync(histp, 0, NN * sizeof(int));
    // kernel order: profiler's fixed slot (4th kernel) lands on the layer-1 GEMM.
    detect_kernel<<<1, 1024>>>((const unsigned int*)ei);                          // 0
    pack_all_kernel<<<(DIN * NT1 + DH1 * NT2 + 255) / 256, 256>>>(
        Wl1, Wr1, Wres1, b1, Wl2, Wr2, Wres2, b2);                                // 1
    xconv_kernel<<<(NN * DIN / 4 + 255) / 256, 256>>>(x);                         // 2
    gemm_tf32_kernel<<<dim3(NT1 / 128, MB), 128>>>(xt, W1p, b1p, c1, NN, DIN, NT1);// 3 <- profiled
    hist_kernel<<<(NE + 255) / 256, 256>>>(ei);                                   // 4
    scan_pass1<<<SCAN_NB, 512>>>();                                               // 5
    scan_pass2<<<1, 128>>>();                                                     // 6
    scan_pass3<<<SCAN_NB, 512>>>();                                               // 7
    scatter_kernel<<<(NE + 255) / 256, 256>>>(ei);                                // 8

    edge_kernel<DH1><<<(NN * 32 + 255) / 256, 256>>>(c1, att1, h1, 1, 1);         // 9

    gemm_tf32_kernel<<<dim3(NT2 / 128, MB), 128>>>((const unsigned*)h1, W2p, b2p,
                                                   c2, NN, DH1, NT2);             // 10
    edge_kernel<DH2><<<(NN * 32 + 255) / 256, 256>>>(c2, att2, (float*)d_out, 0, 0);// 11
}